// round 7
// baseline (speedup 1.0000x reference)
#include <cuda_runtime.h>
#include <math.h>

#define T_TOK 2048
#define DIM   2048
#define NEXP  8
#define FDIM  1408

// ---- device scratch (no allocations allowed) ----
__device__ int   g_cnt[NEXP];
__device__ int   g_tok[NEXP][T_TOK];
__device__ float g_wt [NEXP][T_TOK];
__device__ float g_h  [(size_t)NEXP * T_TOK * FDIM];   // SiLU(xWg)*(xWu)*w

// ---------------------------------------------------------------------------
__device__ __forceinline__ unsigned f2tf32(float x) {
    unsigned r; asm("cvt.rna.tf32.f32 %0, %1;" : "=r"(r) : "f"(x)); return r;
}
__device__ __forceinline__ void mma_tf32(float* c, const unsigned* a, const unsigned* b) {
    asm volatile(
        "mma.sync.aligned.m16n8k8.row.col.f32.tf32.tf32.f32 "
        "{%0,%1,%2,%3}, {%4,%5,%6,%7}, {%8,%9}, {%0,%1,%2,%3};\n"
        : "+f"(c[0]), "+f"(c[1]), "+f"(c[2]), "+f"(c[3])
        : "r"(a[0]), "r"(a[1]), "r"(a[2]), "r"(a[3]), "r"(b[0]), "r"(b[1]));
}

// pack A fragment tile (BM=128 x BK=8): unit(b,g,t) 16B = {(16b+g,k=t),(16b+8+g,t),(16b+g,t+4),(16b+8+g,t+4)}
// stored at unit index b*32 + g*4 + ((t+g)&3); slot within unit = (k>=4?2:0) + ((m>>3)&1)
__device__ __forceinline__ void packA(unsigned* sA, int m, int kq, float4 v) {
    int b = m >> 4, g = m & 7, half = (m >> 3) & 1;
    int slot = (kq ? 2 : 0) + half;
    unsigned base = (unsigned)(b * 32 + g * 4);
    sA[(base + (( g     ) & 3)) * 4 + slot] = f2tf32(v.x);
    sA[(base + ((1 + g  ) & 3)) * 4 + slot] = f2tf32(v.y);
    sA[(base + ((2 + g  ) & 3)) * 4 + slot] = f2tf32(v.z);
    sA[(base + ((3 + g  ) & 3)) * 4 + slot] = f2tf32(v.w);
}
// consume: one LDS.128 per (warp m-block)
__device__ __forceinline__ void fragA(const unsigned* sA, int b, int gid, int tig, unsigned* a) {
    const uint4 v = *reinterpret_cast<const uint4*>(&sA[(unsigned)(b * 32 + gid * 4 + ((tig + gid) & 3)) * 4]);
    a[0] = v.x; a[1] = v.y; a[2] = v.z; a[3] = v.w;
}

// ---------------------------------------------------------------------------
__global__ void zero_kernel(float* __restrict__ out, int n) {
    int i = blockIdx.x * blockDim.x + threadIdx.x;
    if (i < n) out[i] = 0.0f;
    if (blockIdx.x == 0 && threadIdx.x < NEXP) g_cnt[threadIdx.x] = 0;
}

// ---------------------------------------------------------------------------
// router: logits -> softmax -> top2 -> renorm -> scatter to expert lists
// ---------------------------------------------------------------------------
__global__ void router_kernel(const float* __restrict__ x,
                              const float* __restrict__ gw) {
    int t   = blockIdx.x;
    int tid = threadIdx.x;

    float p[NEXP];
#pragma unroll
    for (int e = 0; e < NEXP; e++) p[e] = 0.0f;

    const float* xr = x + (size_t)t * DIM;
    for (int d = tid; d < DIM; d += 128) {
        float xv = xr[d];
#pragma unroll
        for (int e = 0; e < NEXP; e++) p[e] += xv * gw[e * DIM + d];
    }

    __shared__ float sm[NEXP][128];
#pragma unroll
    for (int e = 0; e < NEXP; e++) sm[e][tid] = p[e];
    __syncthreads();

    for (int s = 64; s > 0; s >>= 1) {
        if (tid < s) {
#pragma unroll
            for (int e = 0; e < NEXP; e++) sm[e][tid] += sm[e][tid + s];
        }
        __syncthreads();
    }

    if (tid == 0) {
        float lg[NEXP];
        float mx = -1e30f;
#pragma unroll
        for (int e = 0; e < NEXP; e++) { lg[e] = sm[e][0]; mx = fmaxf(mx, lg[e]); }
        float pr[NEXP];
#pragma unroll
        for (int e = 0; e < NEXP; e++) pr[e] = expf(lg[e] - mx);
        int e0 = 0;
#pragma unroll
        for (int e = 1; e < NEXP; e++) if (pr[e] > pr[e0]) e0 = e;
        int e1 = (e0 == 0) ? 1 : 0;
#pragma unroll
        for (int e = 0; e < NEXP; e++)
            if (e != e0 && pr[e] > pr[e1]) e1 = e;
        float denom = pr[e0] + pr[e1];
        float w0 = pr[e0] / denom;
        float w1 = pr[e1] / denom;
        int p0 = atomicAdd(&g_cnt[e0], 1);
        g_tok[e0][p0] = t; g_wt[e0][p0] = w0;
        int p1 = atomicAdd(&g_cnt[e1], 1);
        g_tok[e1][p1] = t; g_wt[e1][p1] = w1;
    }
}

// ---------------------------------------------------------------------------
// gate+up GEMM: 128 x 128(per matrix) x 8, packed-A, pre-converted B
// 8 warps (2M x 4N), warp tile 64x32 per matrix
// ---------------------------------------------------------------------------
#define GU_BM 128
#define GU_BN 128
#define GU_BK 8
#define GU_BW (GU_BN + 8)    // 136 -> stride mod 32 == 8, conflict-free

__global__ void __launch_bounds__(256, 1)
gateup_mma(const float* __restrict__ x,
           const float* __restrict__ wg,
           const float* __restrict__ wu) {
    int e   = blockIdx.z;
    int cnt = g_cnt[e];
    int m0  = blockIdx.y * GU_BM;
    if (m0 >= cnt) return;
    int n0  = blockIdx.x * GU_BN;

    __shared__ __align__(16) unsigned sA [2][GU_BM * GU_BK];
    __shared__ __align__(16) unsigned sBg[2][GU_BK * GU_BW];
    __shared__ __align__(16) unsigned sBu[2][GU_BK * GU_BW];
    __shared__ int   stok[GU_BM];
    __shared__ float swt[GU_BM];

    int tid = threadIdx.x;
    if (tid < GU_BM) {
        int m = m0 + tid;
        stok[tid] = (m < cnt) ? g_tok[e][m] : 0;
        swt[tid]  = (m < cnt) ? g_wt[e][m]  : 0.0f;
    }
    __syncthreads();

    const float* wgE = wg + (size_t)e * DIM * FDIM;
    const float* wuE = wu + (size_t)e * DIM * FDIM;

    int wid  = tid >> 5, lane = tid & 31;
    int gid  = lane >> 2, tig = lane & 3;
    int warpM = wid & 1, warpN = wid >> 1;       // 2 x 4 warps
    int wm = warpM * 64, wn = warpN * 32;

    // fill assignments
    int arow = tid >> 1, akq = tid & 1;          // A: 1 float4 per thread, k = akq*4..+3
    int bkr  = tid >> 5, bnq = (tid & 31) * 4;   // B: 1 float4 per thread per matrix
    const float* xr0 = x + (size_t)stok[arow] * DIM + akq * 4;

    float cg[4][4][4] = {}, cu[4][4][4] = {};

    const int KT = DIM / GU_BK;     // 256

    // prologue: fill stage 0
    {
        float4 va = *(const float4*)xr0;
        packA(sA[0], arow, akq, va);
        float4 vg = *(const float4*)(wgE + (size_t)bkr * FDIM + n0 + bnq);
        float4 vu = *(const float4*)(wuE + (size_t)bkr * FDIM + n0 + bnq);
        uint4 tg = make_uint4(f2tf32(vg.x), f2tf32(vg.y), f2tf32(vg.z), f2tf32(vg.w));
        uint4 tu = make_uint4(f2tf32(vu.x), f2tf32(vu.y), f2tf32(vu.z), f2tf32(vu.w));
        *(uint4*)&sBg[0][bkr * GU_BW + bnq] = tg;
        *(uint4*)&sBu[0][bkr * GU_BW + bnq] = tu;
    }
    __syncthreads();

    for (int kt = 0; kt < KT; kt++) {
        int cs = kt & 1;
        bool has = (kt + 1 < KT);
        float4 pva, pvg, pvu;
        if (has) {
            int kb = (kt + 1) * GU_BK;
            pva = *(const float4*)(xr0 + kb);
            pvg = *(const float4*)(wgE + (size_t)(kb + bkr) * FDIM + n0 + bnq);
            pvu = *(const float4*)(wuE + (size_t)(kb + bkr) * FDIM + n0 + bnq);
        }

        unsigned a[4][4];
#pragma unroll
        for (int mi = 0; mi < 4; mi++)
            fragA(sA[cs], (wm >> 4) + mi, gid, tig, a[mi]);
#pragma unroll
        for (int ni = 0; ni < 4; ni++) {
            int nc = wn + ni * 8 + gid;
            unsigned bg2[2] = { sBg[cs][tig * GU_BW + nc], sBg[cs][(tig + 4) * GU_BW + nc] };
            unsigned bu2[2] = { sBu[cs][tig * GU_BW + nc], sBu[cs][(tig + 4) * GU_BW + nc] };
#pragma unroll
            for (int mi = 0; mi < 4; mi++) {
                mma_tf32(cg[mi][ni], a[mi], bg2);
                mma_tf32(cu[mi][ni], a[mi], bu2);
            }
        }

        if (has) {
            int ns = cs ^ 1;
            packA(sA[ns], arow, akq, pva);
            uint4 tg = make_uint4(f2tf32(pvg.x), f2tf32(pvg.y), f2tf32(pvg.z), f2tf32(pvg.w));
            uint4 tu = make_uint4(f2tf32(pvu.x), f2tf32(pvu.y), f2tf32(pvu.z), f2tf32(pvu.w));
            *(uint4*)&sBg[ns][bkr * GU_BW + bnq] = tg;
            *(uint4*)&sBu[ns][bkr * GU_BW + bnq] = tu;
        }
        __syncthreads();
    }

    // epilogue: SiLU(g)*u*w -> g_h
#pragma unroll
    for (int mi = 0; mi < 4; mi++) {
#pragma unroll
        for (int half = 0; half < 2; half++) {
            int lm = wm + mi * 16 + gid + half * 8;
            int m  = m0 + lm;
            if (m >= cnt) continue;
            float w = swt[lm];
            float* hrow = g_h + ((size_t)e * T_TOK + m) * FDIM + n0;
#pragma unroll
            for (int ni = 0; ni < 4; ni++) {
                int col = wn + ni * 8 + 2 * tig;
                float g0 = cg[mi][ni][half * 2 + 0], g1 = cg[mi][ni][half * 2 + 1];
                float u0 = cu[mi][ni][half * 2 + 0], u1 = cu[mi][ni][half * 2 + 1];
                float2 hv;
                hv.x = (g0 / (1.0f + __expf(-g0))) * u0 * w;
                hv.y = (g1 / (1.0f + __expf(-g1))) * u1 * w;
                *reinterpret_cast<float2*>(hrow + col) = hv;
            }
        }
    }
}

// ---------------------------------------------------------------------------
// down GEMM + scatter-add: 128 x 256 x 8, packed-A, pre-converted B
// 8 warps (2M x 4N), warp tile 64x64
// ---------------------------------------------------------------------------
#define DN_BM 128
#define DN_BN 256
#define DN_BK 8
#define DN_BW (DN_BN + 8)    // 264 -> stride mod 32 == 8, conflict-free

__global__ void __launch_bounds__(256, 1)
down_mma(const float* __restrict__ wd, float* __restrict__ out) {
    int e   = blockIdx.z;
    int cnt = g_cnt[e];
    int m0  = blockIdx.y * DN_BM;
    if (m0 >= cnt) return;
    int n0  = blockIdx.x * DN_BN;

    __shared__ __align__(16) unsigned sA[2][DN_BM * DN_BK];
    __shared__ __align__(16) unsigned sB[2][DN_BK * DN_BW];
    __shared__ int stok[DN_BM];

    int tid = threadIdx.x;
    if (tid < DN_BM) {
        int m = m0 + tid;
        stok[tid] = (m < cnt) ? g_tok[e][m] : 0;
    }
    __syncthreads();

    const float* wdE = wd + (size_t)e * FDIM * DIM;
    const float* hE  = g_h + (size_t)e * T_TOK * FDIM;

    int wid  = tid >> 5, lane = tid & 31;
    int gid  = lane >> 2, tig = lane & 3;
    int warpM = wid & 1, warpN = wid >> 1;       // 2 x 4 warps, warp tile 64x64
    int wm = warpM * 64, wn = warpN * 64;

    // fill assignments
    int arow = tid >> 1, akq = tid & 1;          // A: 1 float4 per thread
    int bkr  = tid >> 5, bnq = (tid & 31) * 8;   // B: 2 float4 per thread
    const float* hr0 = hE + (size_t)(m0 + arow) * FDIM + akq * 4;

    float c[4][8][4] = {};

    const int KT = FDIM / DN_BK;    // 176

    // prologue: fill stage 0
    {
        float4 va = *(const float4*)hr0;
        packA(sA[0], arow, akq, va);
        const float* bp = wdE + (size_t)bkr * DIM + n0 + bnq;
        float4 v0 = *(const float4*)bp;
        float4 v1 = *(const float4*)(bp + 4);
        *(uint4*)&sB[0][bkr * DN_BW + bnq]     = make_uint4(f2tf32(v0.x), f2tf32(v0.y), f2tf32(v0.z), f2tf32(v0.w));
        *(uint4*)&sB[0][bkr * DN_BW + bnq + 4] = make_uint4(f2tf32(v1.x), f2tf32(v1.y), f2tf32(v1.z), f2tf32(v1.w));
    }
    __syncthreads();

    for (int kt = 0; kt < KT; kt++) {
        int cs = kt & 1;
        bool has = (kt + 1 < KT);
        float4 pva, pv0, pv1;
        if (has) {
            int kb = (kt + 1) * DN_BK;
            pva = *(const float4*)(hr0 + kb);
            const float* bp = wdE + (size_t)(kb + bkr) * DIM + n0 + bnq;
            pv0 = *(const float4*)bp;
            pv1 = *(const float4*)(bp + 4);
        }

        unsigned a[4][4];
#pragma unroll
        for (int mi = 0; mi < 4; mi++)
            fragA(sA[cs], (wm >> 4) + mi, gid, tig, a[mi]);
#pragma unroll
        for (int ni = 0; ni < 8; ni++) {
            int nc = wn + ni * 8 + gid;
            unsigned b2[2] = { sB[cs][tig * DN_BW + nc], sB[cs][(tig + 4) * DN_BW + nc] };
#pragma unroll
            for (int mi = 0; mi < 4; mi++) {
                mma_tf32(c[mi][ni], a[mi], b2);
            }
        }

        if (has) {
            int ns = cs ^ 1;
            packA(sA[ns], arow, akq, pva);
            *(uint4*)&sB[ns][bkr * DN_BW + bnq]     = make_uint4(f2tf32(pv0.x), f2tf32(pv0.y), f2tf32(pv0.z), f2tf32(pv0.w));
            *(uint4*)&sB[ns][bkr * DN_BW + bnq + 4] = make_uint4(f2tf32(pv1.x), f2tf32(pv1.y), f2tf32(pv1.z), f2tf32(pv1.w));
        }
        __syncthreads();
    }

    // epilogue: atomicAdd scatter (exactly 2 adds per out element -> deterministic)
#pragma unroll
    for (int mi = 0; mi < 4; mi++) {
#pragma unroll
        for (int half = 0; half < 2; half++) {
            int lm = wm + mi * 16 + gid + half * 8;
            int m  = m0 + lm;
            if (m >= cnt) continue;
            int tok = stok[lm];
            float* orow = out + (size_t)tok * DIM + n0;
#pragma unroll
            for (int ni = 0; ni < 8; ni++) {
                int col = wn + ni * 8 + 2 * tig;
                atomicAdd(&orow[col + 0], c[mi][ni][half * 2 + 0]);
                atomicAdd(&orow[col + 1], c[mi][ni][half * 2 + 1]);
            }
        }
    }
}

// ---------------------------------------------------------------------------
extern "C" void kernel_launch(void* const* d_in, const int* in_sizes, int n_in,
                              void* d_out, int out_size) {
    const float* x  = (const float*)d_in[0];   // [T, D]
    const float* gw = (const float*)d_in[1];   // [E, D]
    const float* wg = (const float*)d_in[2];   // [E, D, F]
    const float* wu = (const float*)d_in[3];   // [E, D, F]
    const float* wd = (const float*)d_in[4];   // [E, F, D]
    float* out = (float*)d_out;

    int n_out = T_TOK * DIM;
    zero_kernel<<<(n_out + 255) / 256, 256>>>(out, n_out);
    router_kernel<<<T_TOK, 128>>>(x, gw);

    dim3 g2(FDIM / GU_BN, T_TOK / GU_BM, NEXP);   // (11, 16, 8)
    gateup_mma<<<g2, 256>>>(x, wg, wu);

    dim3 g3(DIM / DN_BN, T_TOK / DN_BM, NEXP);    // (8, 16, 8)
    down_mma<<<g3, 256>>>(wd, out);
}

// round 8
// speedup vs baseline: 1.3434x; 1.3434x over previous
#include <cuda_runtime.h>
#include <cuda_fp16.h>
#include <math.h>

#define T_TOK 2048
#define DIM   2048
#define NEXP  8
#define FDIM  1408

// ---- device scratch (no allocations allowed) ----
__device__ int   g_cnt[NEXP];
__device__ int   g_tok[NEXP][T_TOK];
__device__ float g_wt [NEXP][T_TOK];
__device__ float g_h  [(size_t)NEXP * T_TOK * FDIM];   // SiLU(xWg)*(xWu)*w

// ---------------------------------------------------------------------------
__device__ __forceinline__ unsigned pk2(float lo, float hi) {
    __half2 h = __floats2half2_rn(lo, hi);       // low 16 bits <- lo
    return *reinterpret_cast<unsigned*>(&h);
}
__device__ __forceinline__ void mma_f16(float* c, const unsigned* a,
                                        unsigned b0, unsigned b1) {
    asm volatile(
        "mma.sync.aligned.m16n8k16.row.col.f32.f16.f16.f32 "
        "{%0,%1,%2,%3}, {%4,%5,%6,%7}, {%8,%9}, {%0,%1,%2,%3};\n"
        : "+f"(c[0]), "+f"(c[1]), "+f"(c[2]), "+f"(c[3])
        : "r"(a[0]), "r"(a[1]), "r"(a[2]), "r"(a[3]), "r"(b0), "r"(b1));
}
__device__ __forceinline__ void cp16(void* sdst, const void* gsrc) {
    unsigned s = (unsigned)__cvta_generic_to_shared(sdst);
    asm volatile("cp.async.cg.shared.global [%0], [%1], 16;\n" :: "r"(s), "l"(gsrc));
}
__device__ __forceinline__ void cp_commit() { asm volatile("cp.async.commit_group;\n"); }
__device__ __forceinline__ void cp_wait_all() { asm volatile("cp.async.wait_group 0;\n"); }

// ---------------------------------------------------------------------------
__global__ void zero_kernel(float* __restrict__ out, int n) {
    int i = blockIdx.x * blockDim.x + threadIdx.x;
    if (i < n) out[i] = 0.0f;
    if (blockIdx.x == 0 && threadIdx.x < NEXP) g_cnt[threadIdx.x] = 0;
}

// ---------------------------------------------------------------------------
// router: logits -> softmax -> top2 -> renorm -> scatter to expert lists
// ---------------------------------------------------------------------------
__global__ void router_kernel(const float* __restrict__ x,
                              const float* __restrict__ gw) {
    int t   = blockIdx.x;
    int tid = threadIdx.x;

    float p[NEXP];
#pragma unroll
    for (int e = 0; e < NEXP; e++) p[e] = 0.0f;

    const float* xr = x + (size_t)t * DIM;
    for (int d = tid; d < DIM; d += 128) {
        float xv = xr[d];
#pragma unroll
        for (int e = 0; e < NEXP; e++) p[e] += xv * gw[e * DIM + d];
    }

    __shared__ float sm[NEXP][128];
#pragma unroll
    for (int e = 0; e < NEXP; e++) sm[e][tid] = p[e];
    __syncthreads();

    for (int s = 64; s > 0; s >>= 1) {
        if (tid < s) {
#pragma unroll
            for (int e = 0; e < NEXP; e++) sm[e][tid] += sm[e][tid + s];
        }
        __syncthreads();
    }

    if (tid == 0) {
        float lg[NEXP];
        float mx = -1e30f;
#pragma unroll
        for (int e = 0; e < NEXP; e++) { lg[e] = sm[e][0]; mx = fmaxf(mx, lg[e]); }
        float pr[NEXP];
#pragma unroll
        for (int e = 0; e < NEXP; e++) pr[e] = expf(lg[e] - mx);
        int e0 = 0;
#pragma unroll
        for (int e = 1; e < NEXP; e++) if (pr[e] > pr[e0]) e0 = e;
        int e1 = (e0 == 0) ? 1 : 0;
#pragma unroll
        for (int e = 0; e < NEXP; e++)
            if (e != e0 && pr[e] > pr[e1]) e1 = e;
        float denom = pr[e0] + pr[e1];
        float w0 = pr[e0] / denom;
        float w1 = pr[e1] / denom;
        int p0 = atomicAdd(&g_cnt[e0], 1);
        g_tok[e0][p0] = t; g_wt[e0][p0] = w0;
        int p1 = atomicAdd(&g_cnt[e1], 1);
        g_tok[e1][p1] = t; g_wt[e1][p1] = w1;
    }
}

// ---------------------------------------------------------------------------
// gate+up GEMM: tile 128 x 128(per matrix) x 16, fp16 m16n8k16 MMA,
// 8 warps (2M x 4N), 2-stage cp.async
// ---------------------------------------------------------------------------
#define GU_BM 128
#define GU_BN 128
#define GU_BK 16
#define GU_AW (GU_BK + 4)    // 20 floats
#define GU_BW (GU_BN + 8)    // 136 floats

__global__ void __launch_bounds__(256, 1)
gateup_mma(const float* __restrict__ x,
           const float* __restrict__ wg,
           const float* __restrict__ wu) {
    int e   = blockIdx.z;
    int cnt = g_cnt[e];
    int m0  = blockIdx.y * GU_BM;
    if (m0 >= cnt) return;
    int n0  = blockIdx.x * GU_BN;

    __shared__ float As[2][GU_BM][GU_AW];
    __shared__ float Bg[2][GU_BK][GU_BW];
    __shared__ float Bu[2][GU_BK][GU_BW];
    __shared__ int   stok[GU_BM];
    __shared__ float swt[GU_BM];

    int tid = threadIdx.x;
    if (tid < GU_BM) {
        int m = m0 + tid;
        stok[tid] = (m < cnt) ? g_tok[e][m] : 0;
        swt[tid]  = (m < cnt) ? g_wt[e][m]  : 0.0f;
    }
    __syncthreads();

    const float* wgE = wg + (size_t)e * DIM * FDIM;
    const float* wuE = wu + (size_t)e * DIM * FDIM;

    int wid  = tid >> 5, lane = tid & 31;
    int gid  = lane >> 2, tig = lane & 3;
    int warpM = wid & 1, warpN = wid >> 1;       // 2 x 4 warps
    int wm = warpM * 64, wn = warpN * 32;

    // cp.async assignments
    int arow = tid >> 1;            // A: 2 chunks/thread
    int acol = (tid & 1) * 8;
    int bk   = tid >> 5;            // B: 2 chunks/thread/matrix (k = bk, bk+8)
    int bn   = (tid & 31) * 4;

    const float* xr0 = x + (size_t)stok[arow] * DIM + acol;

    float cg[4][4][4] = {}, cu[4][4][4] = {};

    const int KT = DIM / GU_BK;     // 128

    // prologue: stage 0
    {
        cp16(&As[0][arow][acol],     xr0);
        cp16(&As[0][arow][acol + 4], xr0 + 4);
#pragma unroll
        for (int q = 0; q < 2; q++) {
            int k = bk + q * 8;
            cp16(&Bg[0][k][bn], wgE + (size_t)k * FDIM + n0 + bn);
            cp16(&Bu[0][k][bn], wuE + (size_t)k * FDIM + n0 + bn);
        }
        cp_commit();
    }

    for (int kt = 0; kt < KT; kt++) {
        cp_wait_all();
        __syncthreads();

        int ln = kt + 1;
        if (ln < KT) {
            int s  = ln & 1;
            int kb = ln * GU_BK;
            cp16(&As[s][arow][acol],     xr0 + kb);
            cp16(&As[s][arow][acol + 4], xr0 + kb + 4);
#pragma unroll
            for (int q = 0; q < 2; q++) {
                int k = bk + q * 8;
                cp16(&Bg[s][k][bn], wgE + (size_t)(kb + k) * FDIM + n0 + bn);
                cp16(&Bu[s][k][bn], wuE + (size_t)(kb + k) * FDIM + n0 + bn);
            }
            cp_commit();
        }

        int cs = kt & 1;
        int k0 = 2 * tig;
        unsigned a[4][4];
#pragma unroll
        for (int mi = 0; mi < 4; mi++) {
            int r = wm + mi * 16 + gid;
            float2 v0 = *(const float2*)&As[cs][r    ][k0    ];
            float2 v1 = *(const float2*)&As[cs][r + 8][k0    ];
            float2 v2 = *(const float2*)&As[cs][r    ][k0 + 8];
            float2 v3 = *(const float2*)&As[cs][r + 8][k0 + 8];
            a[mi][0] = pk2(v0.x, v0.y);
            a[mi][1] = pk2(v1.x, v1.y);
            a[mi][2] = pk2(v2.x, v2.y);
            a[mi][3] = pk2(v3.x, v3.y);
        }
#pragma unroll
        for (int ni = 0; ni < 4; ni++) {
            int nc = wn + ni * 8 + gid;
            unsigned bg0 = pk2(Bg[cs][k0    ][nc], Bg[cs][k0 + 1][nc]);
            unsigned bg1 = pk2(Bg[cs][k0 + 8][nc], Bg[cs][k0 + 9][nc]);
            unsigned bu0 = pk2(Bu[cs][k0    ][nc], Bu[cs][k0 + 1][nc]);
            unsigned bu1 = pk2(Bu[cs][k0 + 8][nc], Bu[cs][k0 + 9][nc]);
#pragma unroll
            for (int mi = 0; mi < 4; mi++) {
                mma_f16(cg[mi][ni], a[mi], bg0, bg1);
                mma_f16(cu[mi][ni], a[mi], bu0, bu1);
            }
        }
    }

    // epilogue: SiLU(g)*u*w -> g_h
#pragma unroll
    for (int mi = 0; mi < 4; mi++) {
#pragma unroll
        for (int half = 0; half < 2; half++) {
            int lm = wm + mi * 16 + gid + half * 8;
            int m  = m0 + lm;
            if (m >= cnt) continue;
            float w = swt[lm];
            float* hrow = g_h + ((size_t)e * T_TOK + m) * FDIM + n0;
#pragma unroll
            for (int ni = 0; ni < 4; ni++) {
                int col = wn + ni * 8 + 2 * tig;
                float g0 = cg[mi][ni][half * 2 + 0], g1 = cg[mi][ni][half * 2 + 1];
                float u0 = cu[mi][ni][half * 2 + 0], u1 = cu[mi][ni][half * 2 + 1];
                float2 hv;
                hv.x = (g0 / (1.0f + __expf(-g0))) * u0 * w;
                hv.y = (g1 / (1.0f + __expf(-g1))) * u1 * w;
                *reinterpret_cast<float2*>(hrow + col) = hv;
            }
        }
    }
}

// ---------------------------------------------------------------------------
// down GEMM + scatter-add: tile 128 x 256 x 16, fp16 m16n8k16 MMA,
// 8 warps (2M x 4N), warp tile 64x64, 2-stage cp.async
// ---------------------------------------------------------------------------
#define DN_BM 128
#define DN_BN 256
#define DN_BK 16
#define DN_AW (DN_BK + 4)    // 20 floats
#define DN_BW (DN_BN + 8)    // 264 floats

__global__ void __launch_bounds__(256, 1)
down_mma(const float* __restrict__ wd, float* __restrict__ out) {
    int e   = blockIdx.z;
    int cnt = g_cnt[e];
    int m0  = blockIdx.y * DN_BM;
    if (m0 >= cnt) return;
    int n0  = blockIdx.x * DN_BN;

    __shared__ float As[2][DN_BM][DN_AW];
    __shared__ float Bd[2][DN_BK][DN_BW];
    __shared__ int stok[DN_BM];

    int tid = threadIdx.x;
    if (tid < DN_BM) {
        int m = m0 + tid;
        stok[tid] = (m < cnt) ? g_tok[e][m] : 0;
    }
    __syncthreads();

    const float* wdE = wd + (size_t)e * FDIM * DIM;
    const float* hE  = g_h + (size_t)e * T_TOK * FDIM;

    int wid  = tid >> 5, lane = tid & 31;
    int gid  = lane >> 2, tig = lane & 3;
    int warpM = wid & 1, warpN = wid >> 1;       // 2 x 4 warps, warp tile 64x64
    int wm = warpM * 64, wn = warpN * 64;

    // cp.async assignments
    int arow = tid >> 1;            // A: 2 chunks/thread
    int acol = (tid & 1) * 8;
    int bk   = tid >> 6;            // B: 4 chunks/thread (k = bk + q*4)
    int bn   = (tid & 63) * 4;

    const float* hr0 = hE + (size_t)(m0 + arow) * FDIM + acol;

    float c[4][8][4] = {};

    const int KT = FDIM / DN_BK;    // 88

    // prologue: stage 0
    {
        cp16(&As[0][arow][acol],     hr0);
        cp16(&As[0][arow][acol + 4], hr0 + 4);
#pragma unroll
        for (int q = 0; q < 4; q++) {
            int k = bk + q * 4;
            cp16(&Bd[0][k][bn], wdE + (size_t)k * DIM + n0 + bn);
        }
        cp_commit();
    }

    for (int kt = 0; kt < KT; kt++) {
        cp_wait_all();
        __syncthreads();

        int ln = kt + 1;
        if (ln < KT) {
            int s  = ln & 1;
            int kb = ln * DN_BK;
            cp16(&As[s][arow][acol],     hr0 + kb);
            cp16(&As[s][arow][acol + 4], hr0 + kb + 4);
#pragma unroll
            for (int q = 0; q < 4; q++) {
                int k = bk + q * 4;
                cp16(&Bd[s][k][bn], wdE + (size_t)(kb + k) * DIM + n0 + bn);
            }
            cp_commit();
        }

        int cs = kt & 1;
        int k0 = 2 * tig;
        unsigned a[4][4];
#pragma unroll
        for (int mi = 0; mi < 4; mi++) {
            int r = wm + mi * 16 + gid;
            float2 v0 = *(const float2*)&As[cs][r    ][k0    ];
            float2 v1 = *(const float2*)&As[cs][r + 8][k0    ];
            float2 v2 = *(const float2*)&As[cs][r    ][k0 + 8];
            float2 v3 = *(const float2*)&As[cs][r + 8][k0 + 8];
            a[mi][0] = pk2(v0.x, v0.y);
            a[mi][1] = pk2(v1.x, v1.y);
            a[mi][2] = pk2(v2.x, v2.y);
            a[mi][3] = pk2(v3.x, v3.y);
        }
#pragma unroll
        for (int ni = 0; ni < 8; ni++) {
            int nc = wn + ni * 8 + gid;
            unsigned b0 = pk2(Bd[cs][k0    ][nc], Bd[cs][k0 + 1][nc]);
            unsigned b1 = pk2(Bd[cs][k0 + 8][nc], Bd[cs][k0 + 9][nc]);
#pragma unroll
            for (int mi = 0; mi < 4; mi++) {
                mma_f16(c[mi][ni], a[mi], b0, b1);
            }
        }
    }

    // epilogue: atomicAdd scatter (exactly 2 adds per out element -> deterministic)
#pragma unroll
    for (int mi = 0; mi < 4; mi++) {
#pragma unroll
        for (int half = 0; half < 2; half++) {
            int lm = wm + mi * 16 + gid + half * 8;
            int m  = m0 + lm;
            if (m >= cnt) continue;
            int tok = stok[lm];
            float* orow = out + (size_t)tok * DIM + n0;
#pragma unroll
            for (int ni = 0; ni < 8; ni++) {
                int col = wn + ni * 8 + 2 * tig;
                atomicAdd(&orow[col + 0], c[mi][ni][half * 2 + 0]);
                atomicAdd(&orow[col + 1], c[mi][ni][half * 2 + 1]);
            }
        }
    }
}

// ---------------------------------------------------------------------------
extern "C" void kernel_launch(void* const* d_in, const int* in_sizes, int n_in,
                              void* d_out, int out_size) {
    const float* x  = (const float*)d_in[0];   // [T, D]
    const float* gw = (const float*)d_in[1];   // [E, D]
    const float* wg = (const float*)d_in[2];   // [E, D, F]
    const float* wu = (const float*)d_in[3];   // [E, D, F]
    const float* wd = (const float*)d_in[4];   // [E, F, D]
    float* out = (float*)d_out;

    int n_out = T_TOK * DIM;
    zero_kernel<<<(n_out + 255) / 256, 256>>>(out, n_out);
    router_kernel<<<T_TOK, 128>>>(x, gw);

    dim3 g2(FDIM / GU_BN, T_TOK / GU_BM, NEXP);   // (11, 16, 8)
    gateup_mma<<<g2, 256>>>(x, wg, wu);

    dim3 g3(DIM / DN_BN, T_TOK / DN_BM, NEXP);    // (8, 16, 8)
    down_mma<<<g3, 256>>>(wd, out);
}

// round 9
// speedup vs baseline: 2.0870x; 1.5535x over previous
#include <cuda_runtime.h>
#include <cuda_fp16.h>
#include <math.h>

#define T_TOK 2048
#define DIM   2048
#define NEXP  8
#define FDIM  1408
#define D2    (DIM / 2)     // 1024
#define F2    (FDIM / 2)    // 704

// ---- device scratch (no allocations allowed) ----
__device__ int     g_cnt[NEXP];
__device__ int     g_tok[NEXP][T_TOK];
__device__ float   g_wt [NEXP][T_TOK];
__device__ __half  g_xh [(size_t)T_TOK * DIM];              // x as half
__device__ __half2 g_wgi[(size_t)NEXP * D2 * FDIM];         // wg, k-pair interleaved
__device__ __half2 g_wui[(size_t)NEXP * D2 * FDIM];         // wu, k-pair interleaved
__device__ __half2 g_wdi[(size_t)NEXP * F2 * DIM];          // wd, k-pair interleaved
__device__ __half  g_h  [(size_t)NEXP * T_TOK * FDIM];      // SiLU(xWg)*(xWu)*w (half); slots>=cnt stay 0

// ---------------------------------------------------------------------------
__device__ __forceinline__ void mma_f16(float* c, const unsigned* a,
                                        unsigned b0, unsigned b1) {
    asm volatile(
        "mma.sync.aligned.m16n8k16.row.col.f32.f16.f16.f32 "
        "{%0,%1,%2,%3}, {%4,%5,%6,%7}, {%8,%9}, {%0,%1,%2,%3};\n"
        : "+f"(c[0]), "+f"(c[1]), "+f"(c[2]), "+f"(c[3])
        : "r"(a[0]), "r"(a[1]), "r"(a[2]), "r"(a[3]), "r"(b0), "r"(b1));
}
__device__ __forceinline__ void cp16(void* sdst, const void* gsrc) {
    unsigned s = (unsigned)__cvta_generic_to_shared(sdst);
    asm volatile("cp.async.cg.shared.global [%0], [%1], 16;\n" :: "r"(s), "l"(gsrc));
}
__device__ __forceinline__ void cp_commit() { asm volatile("cp.async.commit_group;\n"); }
template <int N>
__device__ __forceinline__ void cp_wait() { asm volatile("cp.async.wait_group %0;\n" :: "n"(N)); }

// ---------------------------------------------------------------------------
__global__ void zero_kernel(float* __restrict__ out, int n) {
    int i = blockIdx.x * blockDim.x + threadIdx.x;
    if (i < n) out[i] = 0.0f;
    if (blockIdx.x == 0 && threadIdx.x < NEXP) g_cnt[threadIdx.x] = 0;
}

// ---------------------------------------------------------------------------
// conversion kernels (run each replay; deterministic)
// ---------------------------------------------------------------------------
__global__ void conv_x(const float* __restrict__ x) {
    size_t i = ((size_t)blockIdx.x * blockDim.x + threadIdx.x) * 8;
    float4 v0 = *(const float4*)(x + i);
    float4 v1 = *(const float4*)(x + i + 4);
    __half2 h[4];
    h[0] = __floats2half2_rn(v0.x, v0.y);
    h[1] = __floats2half2_rn(v0.z, v0.w);
    h[2] = __floats2half2_rn(v1.x, v1.y);
    h[3] = __floats2half2_rn(v1.z, v1.w);
    *(uint4*)(g_xh + i) = *(uint4*)h;
}

// wg/wu: [E][D][F] fp32 -> [E][D/2][F] half2 (pair over D)
__global__ void conv_gu(const float* __restrict__ wg, const float* __restrict__ wu) {
    int id = blockIdx.x * blockDim.x + threadIdx.x;      // E*D2*(F/4) = 2,883,584
    int e   = id / (D2 * (FDIM / 4));
    int rem = id % (D2 * (FDIM / 4));
    int d2  = rem / (FDIM / 4);
    int f   = (rem % (FDIM / 4)) * 4;
    size_t ibase = ((size_t)e * DIM + 2 * d2) * FDIM + f;
    size_t obase = ((size_t)e * D2 + d2) * FDIM + f;
    {
        float4 a0 = *(const float4*)(wg + ibase);
        float4 a1 = *(const float4*)(wg + ibase + FDIM);
        __half2 h[4];
        h[0] = __floats2half2_rn(a0.x, a1.x);
        h[1] = __floats2half2_rn(a0.y, a1.y);
        h[2] = __floats2half2_rn(a0.z, a1.z);
        h[3] = __floats2half2_rn(a0.w, a1.w);
        *(uint4*)(g_wgi + obase) = *(uint4*)h;
    }
    {
        float4 a0 = *(const float4*)(wu + ibase);
        float4 a1 = *(const float4*)(wu + ibase + FDIM);
        __half2 h[4];
        h[0] = __floats2half2_rn(a0.x, a1.x);
        h[1] = __floats2half2_rn(a0.y, a1.y);
        h[2] = __floats2half2_rn(a0.z, a1.z);
        h[3] = __floats2half2_rn(a0.w, a1.w);
        *(uint4*)(g_wui + obase) = *(uint4*)h;
    }
}

// wd: [E][F][D] fp32 -> [E][F/2][D] half2 (pair over F)
__global__ void conv_wd(const float* __restrict__ wd) {
    int id = blockIdx.x * blockDim.x + threadIdx.x;      // E*F2*(D/4) = 2,883,584
    int e   = id / (F2 * (DIM / 4));
    int rem = id % (F2 * (DIM / 4));
    int f2  = rem / (DIM / 4);
    int d   = (rem % (DIM / 4)) * 4;
    size_t ibase = ((size_t)e * FDIM + 2 * f2) * DIM + d;
    float4 a0 = *(const float4*)(wd + ibase);
    float4 a1 = *(const float4*)(wd + ibase + DIM);
    __half2 h[4];
    h[0] = __floats2half2_rn(a0.x, a1.x);
    h[1] = __floats2half2_rn(a0.y, a1.y);
    h[2] = __floats2half2_rn(a0.z, a1.z);
    h[3] = __floats2half2_rn(a0.w, a1.w);
    *(uint4*)(g_wdi + ((size_t)e * F2 + f2) * DIM + d) = *(uint4*)h;
}

// ---------------------------------------------------------------------------
// router: logits -> softmax -> top2 -> renorm -> scatter to expert lists
// ---------------------------------------------------------------------------
__global__ void router_kernel(const float* __restrict__ x,
                              const float* __restrict__ gw) {
    int t   = blockIdx.x;
    int tid = threadIdx.x;

    float p[NEXP];
#pragma unroll
    for (int e = 0; e < NEXP; e++) p[e] = 0.0f;

    const float* xr = x + (size_t)t * DIM;
    for (int d = tid; d < DIM; d += 128) {
        float xv = xr[d];
#pragma unroll
        for (int e = 0; e < NEXP; e++) p[e] += xv * gw[e * DIM + d];
    }

    __shared__ float sm[NEXP][128];
#pragma unroll
    for (int e = 0; e < NEXP; e++) sm[e][tid] = p[e];
    __syncthreads();

    for (int s = 64; s > 0; s >>= 1) {
        if (tid < s) {
#pragma unroll
            for (int e = 0; e < NEXP; e++) sm[e][tid] += sm[e][tid + s];
        }
        __syncthreads();
    }

    if (tid == 0) {
        float lg[NEXP];
        float mx = -1e30f;
#pragma unroll
        for (int e = 0; e < NEXP; e++) { lg[e] = sm[e][0]; mx = fmaxf(mx, lg[e]); }
        float pr[NEXP];
#pragma unroll
        for (int e = 0; e < NEXP; e++) pr[e] = expf(lg[e] - mx);
        int e0 = 0;
#pragma unroll
        for (int e = 1; e < NEXP; e++) if (pr[e] > pr[e0]) e0 = e;
        int e1 = (e0 == 0) ? 1 : 0;
#pragma unroll
        for (int e = 0; e < NEXP; e++)
            if (e != e0 && pr[e] > pr[e1]) e1 = e;
        float denom = pr[e0] + pr[e1];
        float w0 = pr[e0] / denom;
        float w1 = pr[e1] / denom;
        int p0 = atomicAdd(&g_cnt[e0], 1);
        g_tok[e0][p0] = t; g_wt[e0][p0] = w0;
        int p1 = atomicAdd(&g_cnt[e1], 1);
        g_tok[e1][p1] = t; g_wt[e1][p1] = w1;
    }
}

// ---------------------------------------------------------------------------
// smem layouts:
//  A: [BM][24] half   (row stride 12 words -> frag banks 12r+tig all distinct)
//  B: [8][136] half2  (row stride 136 ≡ 8 mod 32 -> banks 8*tig+gid all distinct)
// ---------------------------------------------------------------------------
#define AW 24
#define BW 136

// ---------------------------------------------------------------------------
// gate+up GEMM: 128 x 128(per matrix) x 16, fp16, 3-stage cp.async
// 8 warps (2M x 4N), warp tile 64x32 per matrix
// ---------------------------------------------------------------------------
#define GU_S 3

__global__ void __launch_bounds__(256, 1)
gateup_mma(const float* __restrict__ dummy) {
    int e   = blockIdx.z;
    int cnt = g_cnt[e];
    int m0  = blockIdx.y * 128;
    if (m0 >= cnt) return;
    int n0  = blockIdx.x * 128;

    __shared__ __align__(16) __half  As[GU_S][128][AW];
    __shared__ __align__(16) __half2 Bg[GU_S][8][BW];
    __shared__ __align__(16) __half2 Bu[GU_S][8][BW];
    __shared__ int   stok[128];
    __shared__ float swt[128];

    int tid = threadIdx.x;
    if (tid < 128) {
        int m = m0 + tid;
        stok[tid] = (m < cnt) ? g_tok[e][m] : 0;
        swt[tid]  = (m < cnt) ? g_wt[e][m]  : 0.0f;
    }
    __syncthreads();

    const __half2* wgE = g_wgi + (size_t)e * D2 * FDIM;
    const __half2* wuE = g_wui + (size_t)e * D2 * FDIM;

    int wid  = tid >> 5, lane = tid & 31;
    int gid  = lane >> 2, tig = lane & 3;
    int warpM = wid & 1, warpN = wid >> 1;       // 2 x 4 warps
    int wm = warpM * 64, wn = warpN * 32;

    // fill assignments
    int arow = tid >> 1, acol = (tid & 1) * 8;   // A: 1 chunk (8 halves)
    int bkr  = tid >> 5, bn = (tid & 31) * 4;    // B: 1 chunk (4 half2) per matrix

    const __half* xr0 = g_xh + (size_t)stok[arow] * DIM + acol;

    float cg[4][4][4] = {}, cu[4][4][4] = {};

    const int KT = DIM / 16;     // 128

    // prologue
#pragma unroll
    for (int s = 0; s < GU_S - 1; s++) {
        int kb = s * 16, kb2 = s * 8;
        cp16(&As[s][arow][acol], xr0 + kb);
        cp16(&Bg[s][bkr][bn], wgE + (size_t)(kb2 + bkr) * FDIM + n0 + bn);
        cp16(&Bu[s][bkr][bn], wuE + (size_t)(kb2 + bkr) * FDIM + n0 + bn);
        cp_commit();
    }

    for (int kt = 0; kt < KT; kt++) {
        cp_wait<GU_S - 2>();
        __syncthreads();

        int ln = kt + GU_S - 1;
        if (ln < KT) {
            int s = ln % GU_S;
            int kb = ln * 16, kb2 = ln * 8;
            cp16(&As[s][arow][acol], xr0 + kb);
            cp16(&Bg[s][bkr][bn], wgE + (size_t)(kb2 + bkr) * FDIM + n0 + bn);
            cp16(&Bu[s][bkr][bn], wuE + (size_t)(kb2 + bkr) * FDIM + n0 + bn);
        }
        cp_commit();

        int cs = kt % GU_S;
        int k0 = 2 * tig;
        unsigned a[4][4];
#pragma unroll
        for (int mi = 0; mi < 4; mi++) {
            int r = wm + mi * 16 + gid;
            a[mi][0] = *(const unsigned*)&As[cs][r    ][k0    ];
            a[mi][1] = *(const unsigned*)&As[cs][r + 8][k0    ];
            a[mi][2] = *(const unsigned*)&As[cs][r    ][k0 + 8];
            a[mi][3] = *(const unsigned*)&As[cs][r + 8][k0 + 8];
        }
#pragma unroll
        for (int ni = 0; ni < 4; ni++) {
            int nc = wn + ni * 8 + gid;
            unsigned bg0 = *(const unsigned*)&Bg[cs][tig    ][nc];
            unsigned bg1 = *(const unsigned*)&Bg[cs][tig + 4][nc];
            unsigned bu0 = *(const unsigned*)&Bu[cs][tig    ][nc];
            unsigned bu1 = *(const unsigned*)&Bu[cs][tig + 4][nc];
#pragma unroll
            for (int mi = 0; mi < 4; mi++) {
                mma_f16(cg[mi][ni], a[mi], bg0, bg1);
                mma_f16(cu[mi][ni], a[mi], bu0, bu1);
            }
        }
    }

    // epilogue: SiLU(g)*u*w -> g_h (half)
#pragma unroll
    for (int mi = 0; mi < 4; mi++) {
#pragma unroll
        for (int half = 0; half < 2; half++) {
            int lm = wm + mi * 16 + gid + half * 8;
            int m  = m0 + lm;
            if (m >= cnt) continue;
            float w = swt[lm];
            __half* hrow = g_h + ((size_t)e * T_TOK + m) * FDIM + n0;
#pragma unroll
            for (int ni = 0; ni < 4; ni++) {
                int col = wn + ni * 8 + 2 * tig;
                float g0 = cg[mi][ni][half * 2 + 0], g1 = cg[mi][ni][half * 2 + 1];
                float u0 = cu[mi][ni][half * 2 + 0], u1 = cu[mi][ni][half * 2 + 1];
                float h0 = (g0 / (1.0f + __expf(-g0))) * u0 * w;
                float h1 = (g1 / (1.0f + __expf(-g1))) * u1 * w;
                *(__half2*)(hrow + col) = __floats2half2_rn(h0, h1);
            }
        }
    }
}

// ---------------------------------------------------------------------------
// down GEMM + scatter-add: 128 x 128 x 16, fp16, 4-stage cp.async, 2 CTAs/SM
// 8 warps (2M x 4N), warp tile 64x32
// ---------------------------------------------------------------------------
#define DN_S 4

__global__ void __launch_bounds__(256, 2)
down_mma(float* __restrict__ out) {
    int e   = blockIdx.z;
    int cnt = g_cnt[e];
    int m0  = blockIdx.y * 128;
    if (m0 >= cnt) return;
    int n0  = blockIdx.x * 128;

    __shared__ __align__(16) __half  As[DN_S][128][AW];
    __shared__ __align__(16) __half2 Bd[DN_S][8][BW];
    __shared__ int stok[128];

    int tid = threadIdx.x;
    if (tid < 128) {
        int m = m0 + tid;
        stok[tid] = (m < cnt) ? g_tok[e][m] : 0;
    }
    __syncthreads();

    const __half2* wdE = g_wdi + (size_t)e * F2 * DIM;
    const __half*  hE  = g_h + (size_t)e * T_TOK * FDIM;

    int wid  = tid >> 5, lane = tid & 31;
    int gid  = lane >> 2, tig = lane & 3;
    int warpM = wid & 1, warpN = wid >> 1;       // 2 x 4 warps
    int wm = warpM * 64, wn = warpN * 32;

    int arow = tid >> 1, acol = (tid & 1) * 8;
    int bkr  = tid >> 5, bn = (tid & 31) * 4;

    const __half* hr0 = hE + (size_t)(m0 + arow) * FDIM + acol;

    float c[4][4][4] = {};

    const int KT = FDIM / 16;    // 88

    // prologue
#pragma unroll
    for (int s = 0; s < DN_S - 1; s++) {
        int kb = s * 16, kb2 = s * 8;
        cp16(&As[s][arow][acol], hr0 + kb);
        cp16(&Bd[s][bkr][bn], wdE + (size_t)(kb2 + bkr) * DIM + n0 + bn);
        cp_commit();
    }

    for (int kt = 0; kt < KT; kt++) {
        cp_wait<DN_S - 2>();
        __syncthreads();

        int ln = kt + DN_S - 1;
        if (ln < KT) {
            int s = ln % DN_S;
            int kb = ln * 16, kb2 = ln * 8;
            cp16(&As[s][arow][acol], hr0 + kb);
            cp16(&Bd[s][bkr][bn], wdE + (size_t)(kb2 + bkr) * DIM + n0 + bn);
        }
        cp_commit();

        int cs = kt % DN_S;
        int k0 = 2 * tig;
        unsigned a[4][4];
#pragma unroll
        for (int mi = 0; mi < 4; mi++) {
            int r = wm + mi * 16 + gid;
            a[mi][0] = *(const unsigned*)&As[cs][r    ][k0    ];
            a[mi][1] = *(const unsigned*)&As[cs][r + 8][k0    ];
            a[mi][2] = *(const unsigned*)&As[cs][r    ][k0 + 8];
            a[mi][3] = *(const unsigned*)&As[cs][r + 8][k0 + 8];
        }
#pragma unroll
        for (int ni = 0; ni < 4; ni++) {
            int nc = wn + ni * 8 + gid;
            unsigned b0 = *(const unsigned*)&Bd[cs][tig    ][nc];
            unsigned b1 = *(const unsigned*)&Bd[cs][tig + 4][nc];
#pragma unroll
            for (int mi = 0; mi < 4; mi++) {
                mma_f16(c[mi][ni], a[mi], b0, b1);
            }
        }
    }

    // epilogue: atomicAdd scatter (exactly 2 adds per out element -> deterministic)
#pragma unroll
    for (int mi = 0; mi < 4; mi++) {
#pragma unroll
        for (int half = 0; half < 2; half++) {
            int lm = wm + mi * 16 + gid + half * 8;
            int m  = m0 + lm;
            if (m >= cnt) continue;
            int tok = stok[lm];
            float* orow = out + (size_t)tok * DIM + n0;
#pragma unroll
            for (int ni = 0; ni < 4; ni++) {
                int col = wn + ni * 8 + 2 * tig;
                atomicAdd(&orow[col + 0], c[mi][ni][half * 2 + 0]);
                atomicAdd(&orow[col + 1], c[mi][ni][half * 2 + 1]);
            }
        }
    }
}

// ---------------------------------------------------------------------------
extern "C" void kernel_launch(void* const* d_in, const int* in_sizes, int n_in,
                              void* d_out, int out_size) {
    const float* x  = (const float*)d_in[0];   // [T, D]
    const float* gw = (const float*)d_in[1];   // [E, D]
    const float* wg = (const float*)d_in[2];   // [E, D, F]
    const float* wu = (const float*)d_in[3];   // [E, D, F]
    const float* wd = (const float*)d_in[4];   // [E, F, D]
    float* out = (float*)d_out;

    int n_out = T_TOK * DIM;
    zero_kernel<<<(n_out + 255) / 256, 256>>>(out, n_out);
    conv_x<<<(T_TOK * DIM / 8 + 255) / 256, 256>>>(x);
    conv_gu<<<(NEXP * D2 * (FDIM / 4) + 255) / 256, 256>>>(wg, wu);
    conv_wd<<<(NEXP * F2 * (DIM / 4) + 255) / 256, 256>>>(wd);
    router_kernel<<<T_TOK, 128>>>(x, gw);

    dim3 g2(FDIM / 128, T_TOK / 128, NEXP);   // (11, 16, 8)
    gateup_mma<<<g2, 256>>>(x);

    dim3 g3(DIM / 128, T_TOK / 128, NEXP);    // (16, 16, 8)
    down_mma<<<g3, 256>>>(out);
}

// round 10
// speedup vs baseline: 2.0973x; 1.0050x over previous
#include <cuda_runtime.h>
#include <cuda_fp16.h>
#include <math.h>

#define T_TOK 2048
#define DIM   2048
#define NEXP  8
#define FDIM  1408
#define D2    (DIM / 2)     // 1024
#define F2    (FDIM / 2)    // 704

// ---- device scratch (no allocations allowed) ----
__device__ int     g_cnt[NEXP];
__device__ int     g_tok[NEXP][T_TOK];                      // tok | (which<<12)
__device__ float   g_wt [NEXP][T_TOK];
__device__ __half  g_xh [(size_t)T_TOK * DIM];              // x as half
__device__ __half2 g_wgi[(size_t)NEXP * D2 * FDIM];         // wg, k-pair interleaved
__device__ __half2 g_wui[(size_t)NEXP * D2 * FDIM];         // wu, k-pair interleaved
__device__ __half2 g_wdi[(size_t)NEXP * F2 * DIM];          // wd, k-pair interleaved
__device__ __half  g_h  [(size_t)NEXP * T_TOK * FDIM];      // SiLU(xWg)*(xWu)*w (half)
__device__ float   g_c  [2][(size_t)T_TOK * DIM];           // per-(token,which) down contribs

// ---------------------------------------------------------------------------
__device__ __forceinline__ void mma_f16(float* c, const unsigned* a,
                                        unsigned b0, unsigned b1) {
    asm volatile(
        "mma.sync.aligned.m16n8k16.row.col.f32.f16.f16.f32 "
        "{%0,%1,%2,%3}, {%4,%5,%6,%7}, {%8,%9}, {%0,%1,%2,%3};\n"
        : "+f"(c[0]), "+f"(c[1]), "+f"(c[2]), "+f"(c[3])
        : "r"(a[0]), "r"(a[1]), "r"(a[2]), "r"(a[3]), "r"(b0), "r"(b1));
}
__device__ __forceinline__ void ldsm4(unsigned* a, unsigned addr) {
    asm volatile("ldmatrix.sync.aligned.m8n8.x4.shared.b16 {%0,%1,%2,%3}, [%4];"
        : "=r"(a[0]), "=r"(a[1]), "=r"(a[2]), "=r"(a[3]) : "r"(addr));
}
__device__ __forceinline__ void cp16(void* sdst, const void* gsrc) {
    unsigned s = (unsigned)__cvta_generic_to_shared(sdst);
    asm volatile("cp.async.cg.shared.global [%0], [%1], 16;\n" :: "r"(s), "l"(gsrc));
}
__device__ __forceinline__ void cp_commit() { asm volatile("cp.async.commit_group;\n"); }
template <int N>
__device__ __forceinline__ void cp_wait() { asm volatile("cp.async.wait_group %0;\n" :: "n"(N)); }

// ---------------------------------------------------------------------------
// conversion kernels (run each replay; deterministic)
// ---------------------------------------------------------------------------
__global__ void conv_x(const float* __restrict__ x) {
    if (blockIdx.x == 0 && threadIdx.x < NEXP) g_cnt[threadIdx.x] = 0;
    size_t i = ((size_t)blockIdx.x * blockDim.x + threadIdx.x) * 8;
    float4 v0 = *(const float4*)(x + i);
    float4 v1 = *(const float4*)(x + i + 4);
    __half2 h[4];
    h[0] = __floats2half2_rn(v0.x, v0.y);
    h[1] = __floats2half2_rn(v0.z, v0.w);
    h[2] = __floats2half2_rn(v1.x, v1.y);
    h[3] = __floats2half2_rn(v1.z, v1.w);
    *(uint4*)(g_xh + i) = *(uint4*)h;
}

// wg/wu: [E][D][F] fp32 -> [E][D/2][F] half2 (pair over D)
__global__ void conv_gu(const float* __restrict__ wg, const float* __restrict__ wu) {
    int id = blockIdx.x * blockDim.x + threadIdx.x;
    int e   = id / (D2 * (FDIM / 4));
    int rem = id % (D2 * (FDIM / 4));
    int d2  = rem / (FDIM / 4);
    int f   = (rem % (FDIM / 4)) * 4;
    size_t ibase = ((size_t)e * DIM + 2 * d2) * FDIM + f;
    size_t obase = ((size_t)e * D2 + d2) * FDIM + f;
    {
        float4 a0 = *(const float4*)(wg + ibase);
        float4 a1 = *(const float4*)(wg + ibase + FDIM);
        __half2 h[4];
        h[0] = __floats2half2_rn(a0.x, a1.x);
        h[1] = __floats2half2_rn(a0.y, a1.y);
        h[2] = __floats2half2_rn(a0.z, a1.z);
        h[3] = __floats2half2_rn(a0.w, a1.w);
        *(uint4*)(g_wgi + obase) = *(uint4*)h;
    }
    {
        float4 a0 = *(const float4*)(wu + ibase);
        float4 a1 = *(const float4*)(wu + ibase + FDIM);
        __half2 h[4];
        h[0] = __floats2half2_rn(a0.x, a1.x);
        h[1] = __floats2half2_rn(a0.y, a1.y);
        h[2] = __floats2half2_rn(a0.z, a1.z);
        h[3] = __floats2half2_rn(a0.w, a1.w);
        *(uint4*)(g_wui + obase) = *(uint4*)h;
    }
}

// wd: [E][F][D] fp32 -> [E][F/2][D] half2 (pair over F)
__global__ void conv_wd(const float* __restrict__ wd) {
    int id = blockIdx.x * blockDim.x + threadIdx.x;
    int e   = id / (F2 * (DIM / 4));
    int rem = id % (F2 * (DIM / 4));
    int f2  = rem / (DIM / 4);
    int d   = (rem % (DIM / 4)) * 4;
    size_t ibase = ((size_t)e * FDIM + 2 * f2) * DIM + d;
    float4 a0 = *(const float4*)(wd + ibase);
    float4 a1 = *(const float4*)(wd + ibase + DIM);
    __half2 h[4];
    h[0] = __floats2half2_rn(a0.x, a1.x);
    h[1] = __floats2half2_rn(a0.y, a1.y);
    h[2] = __floats2half2_rn(a0.z, a1.z);
    h[3] = __floats2half2_rn(a0.w, a1.w);
    *(uint4*)(g_wdi + ((size_t)e * F2 + f2) * DIM + d) = *(uint4*)h;
}

// ---------------------------------------------------------------------------
// router: logits -> softmax -> top2 -> renorm -> scatter to expert lists
// ---------------------------------------------------------------------------
__global__ void router_kernel(const float* __restrict__ x,
                              const float* __restrict__ gw) {
    int t   = blockIdx.x;
    int tid = threadIdx.x;

    float p[NEXP];
#pragma unroll
    for (int e = 0; e < NEXP; e++) p[e] = 0.0f;

    const float* xr = x + (size_t)t * DIM;
    for (int d = tid; d < DIM; d += 128) {
        float xv = xr[d];
#pragma unroll
        for (int e = 0; e < NEXP; e++) p[e] += xv * gw[e * DIM + d];
    }

    __shared__ float sm[NEXP][128];
#pragma unroll
    for (int e = 0; e < NEXP; e++) sm[e][tid] = p[e];
    __syncthreads();

    for (int s = 64; s > 0; s >>= 1) {
        if (tid < s) {
#pragma unroll
            for (int e = 0; e < NEXP; e++) sm[e][tid] += sm[e][tid + s];
        }
        __syncthreads();
    }

    if (tid == 0) {
        float lg[NEXP];
        float mx = -1e30f;
#pragma unroll
        for (int e = 0; e < NEXP; e++) { lg[e] = sm[e][0]; mx = fmaxf(mx, lg[e]); }
        float pr[NEXP];
#pragma unroll
        for (int e = 0; e < NEXP; e++) pr[e] = expf(lg[e] - mx);
        int e0 = 0;
#pragma unroll
        for (int e = 1; e < NEXP; e++) if (pr[e] > pr[e0]) e0 = e;
        int e1 = (e0 == 0) ? 1 : 0;
#pragma unroll
        for (int e = 0; e < NEXP; e++)
            if (e != e0 && pr[e] > pr[e1]) e1 = e;
        float denom = pr[e0] + pr[e1];
        float w0 = pr[e0] / denom;
        float w1 = pr[e1] / denom;
        int p0 = atomicAdd(&g_cnt[e0], 1);
        g_tok[e0][p0] = t;          g_wt[e0][p0] = w0;   // which = 0
        int p1 = atomicAdd(&g_cnt[e1], 1);
        g_tok[e1][p1] = t | 4096;   g_wt[e1][p1] = w1;   // which = 1
    }
}

// ---------------------------------------------------------------------------
#define AW 24    // A row: 24 halves (48B) -> LDSM banks (3r)%8 distinct
#define BW 136   // B row: 136 half2 -> stride mod 32 == 8, conflict-free

// ---------------------------------------------------------------------------
// gate+up GEMM: 128 x 128(per matrix) x 16, fp16, 3-stage cp.async, ldmatrix A
// 8 warps (2M x 4N), warp tile 64x32 per matrix
// ---------------------------------------------------------------------------
#define GU_S 3

__global__ void __launch_bounds__(256, 1)
gateup_mma() {
    int e   = blockIdx.z;
    int cnt = g_cnt[e];
    int m0  = blockIdx.y * 128;
    if (m0 >= cnt) return;
    int n0  = blockIdx.x * 128;

    __shared__ __align__(16) __half  As[GU_S][128][AW];
    __shared__ __align__(16) __half2 Bg[GU_S][8][BW];
    __shared__ __align__(16) __half2 Bu[GU_S][8][BW];
    __shared__ int   stok[128];
    __shared__ float swt[128];

    int tid = threadIdx.x;
    if (tid < 128) {
        int m = m0 + tid;
        int v = (m < cnt) ? g_tok[e][m] : 0;
        stok[tid] = v & 4095;
        swt[tid]  = (m < cnt) ? g_wt[e][m] : 0.0f;
    }
    __syncthreads();

    const __half2* wgE = g_wgi + (size_t)e * D2 * FDIM;
    const __half2* wuE = g_wui + (size_t)e * D2 * FDIM;

    int wid  = tid >> 5, lane = tid & 31;
    int gid  = lane >> 2, tig = lane & 3;
    int warpM = wid & 1, warpN = wid >> 1;       // 2 x 4 warps
    int wm = warpM * 64, wn = warpN * 32;

    int arow = tid >> 1, acol = (tid & 1) * 8;
    int bkr  = tid >> 5, bn = (tid & 31) * 4;

    // ldmatrix lane address pieces
    int lrow = wm + (lane & 15), lchunk = (lane >> 4) * 8;

    const __half* xr0 = g_xh + (size_t)stok[arow] * DIM + acol;

    float cg[4][4][4] = {}, cu[4][4][4] = {};

    const int KT = DIM / 16;     // 128

    // prologue
#pragma unroll
    for (int s = 0; s < GU_S - 1; s++) {
        int kb = s * 16, kb2 = s * 8;
        cp16(&As[s][arow][acol], xr0 + kb);
        cp16(&Bg[s][bkr][bn], wgE + (size_t)(kb2 + bkr) * FDIM + n0 + bn);
        cp16(&Bu[s][bkr][bn], wuE + (size_t)(kb2 + bkr) * FDIM + n0 + bn);
        cp_commit();
    }

    for (int kt = 0; kt < KT; kt++) {
        cp_wait<GU_S - 2>();
        __syncthreads();

        int ln = kt + GU_S - 1;
        if (ln < KT) {
            int s = ln % GU_S;
            int kb = ln * 16, kb2 = ln * 8;
            cp16(&As[s][arow][acol], xr0 + kb);
            cp16(&Bg[s][bkr][bn], wgE + (size_t)(kb2 + bkr) * FDIM + n0 + bn);
            cp16(&Bu[s][bkr][bn], wuE + (size_t)(kb2 + bkr) * FDIM + n0 + bn);
        }
        cp_commit();

        int cs = kt % GU_S;
        unsigned abase = (unsigned)__cvta_generic_to_shared(&As[cs][lrow][lchunk]);
        unsigned a[4][4];
#pragma unroll
        for (int mi = 0; mi < 4; mi++)
            ldsm4(a[mi], abase + (unsigned)(mi * 16 * AW * 2));
#pragma unroll
        for (int ni = 0; ni < 4; ni++) {
            int nc = wn + ni * 8 + gid;
            unsigned bg0 = *(const unsigned*)&Bg[cs][tig    ][nc];
            unsigned bg1 = *(const unsigned*)&Bg[cs][tig + 4][nc];
            unsigned bu0 = *(const unsigned*)&Bu[cs][tig    ][nc];
            unsigned bu1 = *(const unsigned*)&Bu[cs][tig + 4][nc];
#pragma unroll
            for (int mi = 0; mi < 4; mi++) {
                mma_f16(cg[mi][ni], a[mi], bg0, bg1);
                mma_f16(cu[mi][ni], a[mi], bu0, bu1);
            }
        }
    }

    // epilogue: SiLU(g)*u*w -> g_h (half)
#pragma unroll
    for (int mi = 0; mi < 4; mi++) {
#pragma unroll
        for (int half = 0; half < 2; half++) {
            int lm = wm + mi * 16 + gid + half * 8;
            int m  = m0 + lm;
            if (m >= cnt) continue;
            float w = swt[lm];
            __half* hrow = g_h + ((size_t)e * T_TOK + m) * FDIM + n0;
#pragma unroll
            for (int ni = 0; ni < 4; ni++) {
                int col = wn + ni * 8 + 2 * tig;
                float g0 = cg[mi][ni][half * 2 + 0], g1 = cg[mi][ni][half * 2 + 1];
                float u0 = cu[mi][ni][half * 2 + 0], u1 = cu[mi][ni][half * 2 + 1];
                float h0 = (g0 / (1.0f + __expf(-g0))) * u0 * w;
                float h1 = (g1 / (1.0f + __expf(-g1))) * u1 * w;
                *(__half2*)(hrow + col) = __floats2half2_rn(h0, h1);
            }
        }
    }
}

// ---------------------------------------------------------------------------
// down GEMM: 128 x 128 x 16, fp16, 4-stage cp.async, 2 CTAs/SM, ldmatrix A
// writes contribution rows to g_c (no atomics)
// ---------------------------------------------------------------------------
#define DN_S 4

__global__ void __launch_bounds__(256, 2)
down_mma() {
    int e   = blockIdx.z;
    int cnt = g_cnt[e];
    int m0  = blockIdx.y * 128;
    if (m0 >= cnt) return;
    int n0  = blockIdx.x * 128;

    __shared__ __align__(16) __half  As[DN_S][128][AW];
    __shared__ __align__(16) __half2 Bd[DN_S][8][BW];
    __shared__ int stok[128];

    int tid = threadIdx.x;
    if (tid < 128) {
        int m = m0 + tid;
        stok[tid] = (m < cnt) ? g_tok[e][m] : 0;
    }
    __syncthreads();

    const __half2* wdE = g_wdi + (size_t)e * F2 * DIM;
    const __half*  hE  = g_h + (size_t)e * T_TOK * FDIM;

    int wid  = tid >> 5, lane = tid & 31;
    int gid  = lane >> 2, tig = lane & 3;
    int warpM = wid & 1, warpN = wid >> 1;
    int wm = warpM * 64, wn = warpN * 32;

    int arow = tid >> 1, acol = (tid & 1) * 8;
    int bkr  = tid >> 5, bn = (tid & 31) * 4;
    int lrow = wm + (lane & 15), lchunk = (lane >> 4) * 8;

    const __half* hr0 = hE + (size_t)(m0 + arow) * FDIM + acol;

    float c[4][4][4] = {};

    const int KT = FDIM / 16;    // 88

    // prologue
#pragma unroll
    for (int s = 0; s < DN_S - 1; s++) {
        int kb = s * 16, kb2 = s * 8;
        cp16(&As[s][arow][acol], hr0 + kb);
        cp16(&Bd[s][bkr][bn], wdE + (size_t)(kb2 + bkr) * DIM + n0 + bn);
        cp_commit();
    }

    for (int kt = 0; kt < KT; kt++) {
        cp_wait<DN_S - 2>();
        __syncthreads();

        int ln = kt + DN_S - 1;
        if (ln < KT) {
            int s = ln % DN_S;
            int kb = ln * 16, kb2 = ln * 8;
            cp16(&As[s][arow][acol], hr0 + kb);
            cp16(&Bd[s][bkr][bn], wdE + (size_t)(kb2 + bkr) * DIM + n0 + bn);
        }
        cp_commit();

        int cs = kt % DN_S;
        unsigned abase = (unsigned)__cvta_generic_to_shared(&As[cs][lrow][lchunk]);
        unsigned a[4][4];
#pragma unroll
        for (int mi = 0; mi < 4; mi++)
            ldsm4(a[mi], abase + (unsigned)(mi * 16 * AW * 2));
#pragma unroll
        for (int ni = 0; ni < 4; ni++) {
            int nc = wn + ni * 8 + gid;
            unsigned b0 = *(const unsigned*)&Bd[cs][tig    ][nc];
            unsigned b1 = *(const unsigned*)&Bd[cs][tig + 4][nc];
#pragma unroll
            for (int mi = 0; mi < 4; mi++) {
                mma_f16(c[mi][ni], a[mi], b0, b1);
            }
        }
    }

    // epilogue: write contribution rows (plain stores, no atomics)
#pragma unroll
    for (int mi = 0; mi < 4; mi++) {
#pragma unroll
        for (int half = 0; half < 2; half++) {
            int lm = wm + mi * 16 + gid + half * 8;
            int m  = m0 + lm;
            if (m >= cnt) continue;
            int v = stok[lm];
            int tok = v & 4095, which = v >> 12;
            float* crow = &g_c[which][(size_t)tok * DIM + n0];
#pragma unroll
            for (int ni = 0; ni < 4; ni++) {
                int col = wn + ni * 8 + 2 * tig;
                float2 o;
                o.x = c[mi][ni][half * 2 + 0];
                o.y = c[mi][ni][half * 2 + 1];
                *(float2*)(crow + col) = o;
            }
        }
    }
}

// ---------------------------------------------------------------------------
// combine: out[t] = contrib[0][t] + contrib[1][t]  (fixed order, deterministic)
// ---------------------------------------------------------------------------
__global__ void combine_kernel(float* __restrict__ out) {
    size_t i = ((size_t)blockIdx.x * blockDim.x + threadIdx.x) * 4;
    float4 a = *(const float4*)&g_c[0][i];
    float4 b = *(const float4*)&g_c[1][i];
    float4 o;
    o.x = a.x + b.x; o.y = a.y + b.y; o.z = a.z + b.z; o.w = a.w + b.w;
    *(float4*)(out + i) = o;
}

// ---------------------------------------------------------------------------
extern "C" void kernel_launch(void* const* d_in, const int* in_sizes, int n_in,
                              void* d_out, int out_size) {
    const float* x  = (const float*)d_in[0];   // [T, D]
    const float* gw = (const float*)d_in[1];   // [E, D]
    const float* wg = (const float*)d_in[2];   // [E, D, F]
    const float* wu = (const float*)d_in[3];   // [E, D, F]
    const float* wd = (const float*)d_in[4];   // [E, F, D]
    float* out = (float*)d_out;

    conv_x<<<(T_TOK * DIM / 8 + 255) / 256, 256>>>(x);
    conv_gu<<<(NEXP * D2 * (FDIM / 4) + 255) / 256, 256>>>(wg, wu);
    conv_wd<<<(NEXP * F2 * (DIM / 4) + 255) / 256, 256>>>(wd);
    router_kernel<<<T_TOK, 128>>>(x, gw);

    dim3 g2(FDIM / 128, T_TOK / 128, NEXP);   // (11, 16, 8)
    gateup_mma<<<g2, 256>>>();

    dim3 g3(DIM / 128, T_TOK / 128, NEXP);    // (16, 16, 8)
    down_mma<<<g3, 256>>>();

    combine_kernel<<<(T_TOK * DIM) / (256 * 4), 256>>>(out);
}

// round 11
// speedup vs baseline: 2.1074x; 1.0048x over previous
#include <cuda_runtime.h>
#include <cuda_fp16.h>
#include <math.h>

#define T_TOK 2048
#define DIM   2048
#define NEXP  8
#define FDIM  1408
#define D2    (DIM / 2)     // 1024
#define F2    (FDIM / 2)    // 704

// ---- device scratch (no allocations allowed) ----
__device__ int     g_cnt[NEXP];
__device__ int     g_tok[NEXP][T_TOK];                      // tok | (which<<12)
__device__ float   g_wt [NEXP][T_TOK];
__device__ __half  g_xh [(size_t)T_TOK * DIM];              // x as half
__device__ __half2 g_wgi[(size_t)NEXP * D2 * FDIM];         // wg, k-pair interleaved
__device__ __half2 g_wui[(size_t)NEXP * D2 * FDIM];         // wu, k-pair interleaved
__device__ __half2 g_wdi[(size_t)NEXP * F2 * DIM];          // wd, k-pair interleaved
__device__ __half  g_h  [(size_t)NEXP * T_TOK * FDIM];      // SiLU(xWg)*(xWu)*w (half)
__device__ float   g_c  [2][(size_t)T_TOK * DIM];           // per-(token,which) down contribs

// ---------------------------------------------------------------------------
__device__ __forceinline__ void mma_f16(float* c, const unsigned* a,
                                        unsigned b0, unsigned b1) {
    asm volatile(
        "mma.sync.aligned.m16n8k16.row.col.f32.f16.f16.f32 "
        "{%0,%1,%2,%3}, {%4,%5,%6,%7}, {%8,%9}, {%0,%1,%2,%3};\n"
        : "+f"(c[0]), "+f"(c[1]), "+f"(c[2]), "+f"(c[3])
        : "r"(a[0]), "r"(a[1]), "r"(a[2]), "r"(a[3]), "r"(b0), "r"(b1));
}
__device__ __forceinline__ void ldsm4(unsigned* a, unsigned addr) {
    asm volatile("ldmatrix.sync.aligned.m8n8.x4.shared.b16 {%0,%1,%2,%3}, [%4];"
        : "=r"(a[0]), "=r"(a[1]), "=r"(a[2]), "=r"(a[3]) : "r"(addr));
}
__device__ __forceinline__ void cp16(void* sdst, const void* gsrc) {
    unsigned s = (unsigned)__cvta_generic_to_shared(sdst);
    asm volatile("cp.async.cg.shared.global [%0], [%1], 16;\n" :: "r"(s), "l"(gsrc));
}
__device__ __forceinline__ void cp_commit() { asm volatile("cp.async.commit_group;\n"); }
template <int N>
__device__ __forceinline__ void cp_wait() { asm volatile("cp.async.wait_group %0;\n" :: "n"(N)); }

// ---------------------------------------------------------------------------
// conversion kernels (run each replay; deterministic)
// ---------------------------------------------------------------------------
__global__ void conv_x(const float* __restrict__ x) {
    if (blockIdx.x == 0 && threadIdx.x < NEXP) g_cnt[threadIdx.x] = 0;
    size_t i = ((size_t)blockIdx.x * blockDim.x + threadIdx.x) * 8;
    float4 v0 = *(const float4*)(x + i);
    float4 v1 = *(const float4*)(x + i + 4);
    __half2 h[4];
    h[0] = __floats2half2_rn(v0.x, v0.y);
    h[1] = __floats2half2_rn(v0.z, v0.w);
    h[2] = __floats2half2_rn(v1.x, v1.y);
    h[3] = __floats2half2_rn(v1.z, v1.w);
    *(uint4*)(g_xh + i) = *(uint4*)h;
}

// wg/wu: [E][D][F] fp32 -> [E][D/2][F] half2 (pair over D)
__global__ void conv_gu(const float* __restrict__ wg, const float* __restrict__ wu) {
    int id = blockIdx.x * blockDim.x + threadIdx.x;
    int e   = id / (D2 * (FDIM / 4));
    int rem = id % (D2 * (FDIM / 4));
    int d2  = rem / (FDIM / 4);
    int f   = (rem % (FDIM / 4)) * 4;
    size_t ibase = ((size_t)e * DIM + 2 * d2) * FDIM + f;
    size_t obase = ((size_t)e * D2 + d2) * FDIM + f;
    {
        float4 a0 = *(const float4*)(wg + ibase);
        float4 a1 = *(const float4*)(wg + ibase + FDIM);
        __half2 h[4];
        h[0] = __floats2half2_rn(a0.x, a1.x);
        h[1] = __floats2half2_rn(a0.y, a1.y);
        h[2] = __floats2half2_rn(a0.z, a1.z);
        h[3] = __floats2half2_rn(a0.w, a1.w);
        *(uint4*)(g_wgi + obase) = *(uint4*)h;
    }
    {
        float4 a0 = *(const float4*)(wu + ibase);
        float4 a1 = *(const float4*)(wu + ibase + FDIM);
        __half2 h[4];
        h[0] = __floats2half2_rn(a0.x, a1.x);
        h[1] = __floats2half2_rn(a0.y, a1.y);
        h[2] = __floats2half2_rn(a0.z, a1.z);
        h[3] = __floats2half2_rn(a0.w, a1.w);
        *(uint4*)(g_wui + obase) = *(uint4*)h;
    }
}

// wd: [E][F][D] fp32 -> [E][F/2][D] half2 (pair over F)
__global__ void conv_wd(const float* __restrict__ wd) {
    int id = blockIdx.x * blockDim.x + threadIdx.x;
    int e   = id / (F2 * (DIM / 4));
    int rem = id % (F2 * (DIM / 4));
    int f2  = rem / (DIM / 4);
    int d   = (rem % (DIM / 4)) * 4;
    size_t ibase = ((size_t)e * FDIM + 2 * f2) * DIM + d;
    float4 a0 = *(const float4*)(wd + ibase);
    float4 a1 = *(const float4*)(wd + ibase + DIM);
    __half2 h[4];
    h[0] = __floats2half2_rn(a0.x, a1.x);
    h[1] = __floats2half2_rn(a0.y, a1.y);
    h[2] = __floats2half2_rn(a0.z, a1.z);
    h[3] = __floats2half2_rn(a0.w, a1.w);
    *(uint4*)(g_wdi + ((size_t)e * F2 + f2) * DIM + d) = *(uint4*)h;
}

// ---------------------------------------------------------------------------
// router: logits -> softmax -> top2 -> renorm -> scatter to expert lists
// ---------------------------------------------------------------------------
__global__ void router_kernel(const float* __restrict__ x,
                              const float* __restrict__ gw) {
    int t   = blockIdx.x;
    int tid = threadIdx.x;

    float p[NEXP];
#pragma unroll
    for (int e = 0; e < NEXP; e++) p[e] = 0.0f;

    const float* xr = x + (size_t)t * DIM;
    for (int d = tid; d < DIM; d += 128) {
        float xv = xr[d];
#pragma unroll
        for (int e = 0; e < NEXP; e++) p[e] += xv * gw[e * DIM + d];
    }

    __shared__ float sm[NEXP][128];
#pragma unroll
    for (int e = 0; e < NEXP; e++) sm[e][tid] = p[e];
    __syncthreads();

    for (int s = 64; s > 0; s >>= 1) {
        if (tid < s) {
#pragma unroll
            for (int e = 0; e < NEXP; e++) sm[e][tid] += sm[e][tid + s];
        }
        __syncthreads();
    }

    if (tid == 0) {
        float lg[NEXP];
        float mx = -1e30f;
#pragma unroll
        for (int e = 0; e < NEXP; e++) { lg[e] = sm[e][0]; mx = fmaxf(mx, lg[e]); }
        float pr[NEXP];
#pragma unroll
        for (int e = 0; e < NEXP; e++) pr[e] = expf(lg[e] - mx);
        int e0 = 0;
#pragma unroll
        for (int e = 1; e < NEXP; e++) if (pr[e] > pr[e0]) e0 = e;
        int e1 = (e0 == 0) ? 1 : 0;
#pragma unroll
        for (int e = 0; e < NEXP; e++)
            if (e != e0 && pr[e] > pr[e1]) e1 = e;
        float denom = pr[e0] + pr[e1];
        float w0 = pr[e0] / denom;
        float w1 = pr[e1] / denom;
        int p0 = atomicAdd(&g_cnt[e0], 1);
        g_tok[e0][p0] = t;          g_wt[e0][p0] = w0;   // which = 0
        int p1 = atomicAdd(&g_cnt[e1], 1);
        g_tok[e1][p1] = t | 4096;   g_wt[e1][p1] = w1;   // which = 1
    }
}

// ---------------------------------------------------------------------------
#define AW 24    // A row: 24 halves (48B) -> LDSM banks conflict-free
#define BW 136   // B row: 136 half2 -> stride mod 32 == 8, conflict-free

// ---------------------------------------------------------------------------
// gate+up GEMM: 128 x 128(per matrix) x 16, fp16, 3-stage cp.async, ldmatrix A
// 512 threads, 16 warps (2M x 8N), warp tile 64x16 per matrix
// ---------------------------------------------------------------------------
#define GU_S 3

__global__ void __launch_bounds__(512, 1)
gateup_mma() {
    int e   = blockIdx.z;
    int cnt = g_cnt[e];
    int m0  = blockIdx.y * 128;
    if (m0 >= cnt) return;
    int n0  = blockIdx.x * 128;

    __shared__ __align__(16) __half  As[GU_S][128][AW];
    __shared__ __align__(16) __half2 Bg[GU_S][8][BW];
    __shared__ __align__(16) __half2 Bu[GU_S][8][BW];
    __shared__ int   stok[128];
    __shared__ float swt[128];

    int tid = threadIdx.x;
    if (tid < 128) {
        int m = m0 + tid;
        int v = (m < cnt) ? g_tok[e][m] : 0;
        stok[tid] = v & 4095;
        swt[tid]  = (m < cnt) ? g_wt[e][m] : 0.0f;
    }
    __syncthreads();

    const __half2* wgE = g_wgi + (size_t)e * D2 * FDIM;
    const __half2* wuE = g_wui + (size_t)e * D2 * FDIM;

    int wid  = tid >> 5, lane = tid & 31;
    int gid  = lane >> 2, tig = lane & 3;
    int warpM = wid & 1, warpN = wid >> 1;       // 2 x 8 warps
    int wm = warpM * 64, wn = warpN * 16;

    // fill assignments: tid<256 -> A (1 chunk); tid>=256 -> Bg+Bu (1 chunk each)
    bool isA = tid < 256;
    int arow = tid >> 1, acol = (tid & 1) * 8;                  // for tid<256
    int bt   = tid - 256;
    int bkr  = bt >> 5, bn = (bt & 31) * 4;                     // for tid>=256

    // ldmatrix lane address pieces
    int lrow = wm + (lane & 15), lchunk = (lane >> 4) * 8;

    const __half* xr0 = isA ? (g_xh + (size_t)stok[arow] * DIM + acol) : g_xh;

    float cg[4][2][4] = {}, cu[4][2][4] = {};

    const int KT = DIM / 16;     // 128

    // prologue
#pragma unroll
    for (int s = 0; s < GU_S - 1; s++) {
        int kb = s * 16, kb2 = s * 8;
        if (isA) {
            cp16(&As[s][arow][acol], xr0 + kb);
        } else {
            cp16(&Bg[s][bkr][bn], wgE + (size_t)(kb2 + bkr) * FDIM + n0 + bn);
            cp16(&Bu[s][bkr][bn], wuE + (size_t)(kb2 + bkr) * FDIM + n0 + bn);
        }
        cp_commit();
    }

    for (int kt = 0; kt < KT; kt++) {
        cp_wait<GU_S - 2>();
        __syncthreads();

        int ln = kt + GU_S - 1;
        if (ln < KT) {
            int s = ln % GU_S;
            int kb = ln * 16, kb2 = ln * 8;
            if (isA) {
                cp16(&As[s][arow][acol], xr0 + kb);
            } else {
                cp16(&Bg[s][bkr][bn], wgE + (size_t)(kb2 + bkr) * FDIM + n0 + bn);
                cp16(&Bu[s][bkr][bn], wuE + (size_t)(kb2 + bkr) * FDIM + n0 + bn);
            }
        }
        cp_commit();

        int cs = kt % GU_S;
        unsigned abase = (unsigned)__cvta_generic_to_shared(&As[cs][lrow][lchunk]);
        unsigned a[4][4];
#pragma unroll
        for (int mi = 0; mi < 4; mi++)
            ldsm4(a[mi], abase + (unsigned)(mi * 16 * AW * 2));
#pragma unroll
        for (int ni = 0; ni < 2; ni++) {
            int nc = wn + ni * 8 + gid;
            unsigned bg0 = *(const unsigned*)&Bg[cs][tig    ][nc];
            unsigned bg1 = *(const unsigned*)&Bg[cs][tig + 4][nc];
            unsigned bu0 = *(const unsigned*)&Bu[cs][tig    ][nc];
            unsigned bu1 = *(const unsigned*)&Bu[cs][tig + 4][nc];
#pragma unroll
            for (int mi = 0; mi < 4; mi++) {
                mma_f16(cg[mi][ni], a[mi], bg0, bg1);
                mma_f16(cu[mi][ni], a[mi], bu0, bu1);
            }
        }
    }

    // epilogue: SiLU(g)*u*w -> g_h (half)
#pragma unroll
    for (int mi = 0; mi < 4; mi++) {
#pragma unroll
        for (int half = 0; half < 2; half++) {
            int lm = wm + mi * 16 + gid + half * 8;
            int m  = m0 + lm;
            if (m >= cnt) continue;
            float w = swt[lm];
            __half* hrow = g_h + ((size_t)e * T_TOK + m) * FDIM + n0;
#pragma unroll
            for (int ni = 0; ni < 2; ni++) {
                int col = wn + ni * 8 + 2 * tig;
                float g0 = cg[mi][ni][half * 2 + 0], g1 = cg[mi][ni][half * 2 + 1];
                float u0 = cu[mi][ni][half * 2 + 0], u1 = cu[mi][ni][half * 2 + 1];
                float h0 = (g0 / (1.0f + __expf(-g0))) * u0 * w;
                float h1 = (g1 / (1.0f + __expf(-g1))) * u1 * w;
                *(__half2*)(hrow + col) = __floats2half2_rn(h0, h1);
            }
        }
    }
}

// ---------------------------------------------------------------------------
// down GEMM: 128 x 128 x 16, fp16, 4-stage cp.async, 2 CTAs/SM, ldmatrix A
// writes contribution rows to g_c (no atomics)
// ---------------------------------------------------------------------------
#define DN_S 4

__global__ void __launch_bounds__(256, 2)
down_mma() {
    int e   = blockIdx.z;
    int cnt = g_cnt[e];
    int m0  = blockIdx.y * 128;
    if (m0 >= cnt) return;
    int n0  = blockIdx.x * 128;

    __shared__ __align__(16) __half  As[DN_S][128][AW];
    __shared__ __align__(16) __half2 Bd[DN_S][8][BW];
    __shared__ int stok[128];

    int tid = threadIdx.x;
    if (tid < 128) {
        int m = m0 + tid;
        stok[tid] = (m < cnt) ? g_tok[e][m] : 0;
    }
    __syncthreads();

    const __half2* wdE = g_wdi + (size_t)e * F2 * DIM;
    const __half*  hE  = g_h + (size_t)e * T_TOK * FDIM;

    int wid  = tid >> 5, lane = tid & 31;
    int gid  = lane >> 2, tig = lane & 3;
    int warpM = wid & 1, warpN = wid >> 1;
    int wm = warpM * 64, wn = warpN * 32;

    int arow = tid >> 1, acol = (tid & 1) * 8;
    int bkr  = tid >> 5, bn = (tid & 31) * 4;
    int lrow = wm + (lane & 15), lchunk = (lane >> 4) * 8;

    const __half* hr0 = hE + (size_t)(m0 + arow) * FDIM + acol;

    float c[4][4][4] = {};

    const int KT = FDIM / 16;    // 88

    // prologue
#pragma unroll
    for (int s = 0; s < DN_S - 1; s++) {
        int kb = s * 16, kb2 = s * 8;
        cp16(&As[s][arow][acol], hr0 + kb);
        cp16(&Bd[s][bkr][bn], wdE + (size_t)(kb2 + bkr) * DIM + n0 + bn);
        cp_commit();
    }

    for (int kt = 0; kt < KT; kt++) {
        cp_wait<DN_S - 2>();
        __syncthreads();

        int ln = kt + DN_S - 1;
        if (ln < KT) {
            int s = ln % DN_S;
            int kb = ln * 16, kb2 = ln * 8;
            cp16(&As[s][arow][acol], hr0 + kb);
            cp16(&Bd[s][bkr][bn], wdE + (size_t)(kb2 + bkr) * DIM + n0 + bn);
        }
        cp_commit();

        int cs = kt % DN_S;
        unsigned abase = (unsigned)__cvta_generic_to_shared(&As[cs][lrow][lchunk]);
        unsigned a[4][4];
#pragma unroll
        for (int mi = 0; mi < 4; mi++)
            ldsm4(a[mi], abase + (unsigned)(mi * 16 * AW * 2));
#pragma unroll
        for (int ni = 0; ni < 4; ni++) {
            int nc = wn + ni * 8 + gid;
            unsigned b0 = *(const unsigned*)&Bd[cs][tig    ][nc];
            unsigned b1 = *(const unsigned*)&Bd[cs][tig + 4][nc];
#pragma unroll
            for (int mi = 0; mi < 4; mi++) {
                mma_f16(c[mi][ni], a[mi], b0, b1);
            }
        }
    }

    // epilogue: write contribution rows (plain stores, no atomics)
#pragma unroll
    for (int mi = 0; mi < 4; mi++) {
#pragma unroll
        for (int half = 0; half < 2; half++) {
            int lm = wm + mi * 16 + gid + half * 8;
            int m  = m0 + lm;
            if (m >= cnt) continue;
            int v = stok[lm];
            int tok = v & 4095, which = v >> 12;
            float* crow = &g_c[which][(size_t)tok * DIM + n0];
#pragma unroll
            for (int ni = 0; ni < 4; ni++) {
                int col = wn + ni * 8 + 2 * tig;
                float2 o;
                o.x = c[mi][ni][half * 2 + 0];
                o.y = c[mi][ni][half * 2 + 1];
                *(float2*)(crow + col) = o;
            }
        }
    }
}

// ---------------------------------------------------------------------------
// combine: out[t] = contrib[0][t] + contrib[1][t]  (fixed order, deterministic)
// ---------------------------------------------------------------------------
__global__ void combine_kernel(float* __restrict__ out) {
    size_t i = ((size_t)blockIdx.x * blockDim.x + threadIdx.x) * 4;
    float4 a = *(const float4*)&g_c[0][i];
    float4 b = *(const float4*)&g_c[1][i];
    float4 o;
    o.x = a.x + b.x; o.y = a.y + b.y; o.z = a.z + b.z; o.w = a.w + b.w;
    *(float4*)(out + i) = o;
}

// ---------------------------------------------------------------------------
extern "C" void kernel_launch(void* const* d_in, const int* in_sizes, int n_in,
                              void* d_out, int out_size) {
    const float* x  = (const float*)d_in[0];   // [T, D]
    const float* gw = (const float*)d_in[1];   // [E, D]
    const float* wg = (const float*)d_in[2];   // [E, D, F]
    const float* wu = (const float*)d_in[3];   // [E, D, F]
    const float* wd = (const float*)d_in[4];   // [E, F, D]
    float* out = (float*)d_out;

    conv_x<<<(T_TOK * DIM / 8 + 255) / 256, 256>>>(x);
    conv_gu<<<(NEXP * D2 * (FDIM / 4) + 255) / 256, 256>>>(wg, wu);
    conv_wd<<<(NEXP * F2 * (DIM / 4) + 255) / 256, 256>>>(wd);
    router_kernel<<<T_TOK, 128>>>(x, gw);

    dim3 g2(FDIM / 128, T_TOK / 128, NEXP);   // (11, 16, 8)
    gateup_mma<<<g2, 512>>>();

    dim3 g3(DIM / 128, T_TOK / 128, NEXP);    // (16, 16, 8)
    down_mma<<<g3, 256>>>();

    combine_kernel<<<(T_TOK * DIM) / (256 * 4), 256>>>(out);
}

// round 12
// speedup vs baseline: 2.2060x; 1.0468x over previous
#include <cuda_runtime.h>
#include <cuda_fp16.h>
#include <math.h>

#define T_TOK 2048
#define DIM   2048
#define NEXP  8
#define FDIM  1408
#define D2    (DIM / 2)     // 1024
#define F2    (FDIM / 2)    // 704

// ---- device scratch (no allocations allowed) ----
__device__ int     g_cnt[NEXP];
__device__ int     g_tok[NEXP][T_TOK];                      // tok | (which<<12)
__device__ float   g_wt [NEXP][T_TOK];
__device__ __half  g_xh [(size_t)T_TOK * DIM];              // x as half
__device__ __half2 g_wgi[(size_t)NEXP * D2 * FDIM];         // wg, k-pair interleaved
__device__ __half2 g_wui[(size_t)NEXP * D2 * FDIM];         // wu, k-pair interleaved
__device__ __half2 g_wdi[(size_t)NEXP * F2 * DIM];          // wd, k-pair interleaved
__device__ __half  g_h  [(size_t)NEXP * T_TOK * FDIM];      // SiLU(xWg)*(xWu)*w (half)
__device__ float   g_c  [2][(size_t)T_TOK * DIM];           // per-(token,which) down contribs

// ---------------------------------------------------------------------------
__device__ __forceinline__ void mma_f16(float* c, const unsigned* a,
                                        unsigned b0, unsigned b1) {
    asm volatile(
        "mma.sync.aligned.m16n8k16.row.col.f32.f16.f16.f32 "
        "{%0,%1,%2,%3}, {%4,%5,%6,%7}, {%8,%9}, {%0,%1,%2,%3};\n"
        : "+f"(c[0]), "+f"(c[1]), "+f"(c[2]), "+f"(c[3])
        : "r"(a[0]), "r"(a[1]), "r"(a[2]), "r"(a[3]), "r"(b0), "r"(b1));
}
__device__ __forceinline__ void ldsm4(unsigned* a, unsigned addr) {
    asm volatile("ldmatrix.sync.aligned.m8n8.x4.shared.b16 {%0,%1,%2,%3}, [%4];"
        : "=r"(a[0]), "=r"(a[1]), "=r"(a[2]), "=r"(a[3]) : "r"(addr));
}
__device__ __forceinline__ void cp16(void* sdst, const void* gsrc) {
    unsigned s = (unsigned)__cvta_generic_to_shared(sdst);
    asm volatile("cp.async.cg.shared.global [%0], [%1], 16;\n" :: "r"(s), "l"(gsrc));
}
__device__ __forceinline__ void cp_commit() { asm volatile("cp.async.commit_group;\n"); }
template <int N>
__device__ __forceinline__ void cp_wait() { asm volatile("cp.async.wait_group %0;\n" :: "n"(N)); }

// ---------------------------------------------------------------------------
// conversion kernels (run each replay; deterministic)
// ---------------------------------------------------------------------------
__global__ void conv_x(const float* __restrict__ x) {
    if (blockIdx.x == 0 && threadIdx.x < NEXP) g_cnt[threadIdx.x] = 0;
    size_t i = ((size_t)blockIdx.x * blockDim.x + threadIdx.x) * 8;
    float4 v0 = *(const float4*)(x + i);
    float4 v1 = *(const float4*)(x + i + 4);
    __half2 h[4];
    h[0] = __floats2half2_rn(v0.x, v0.y);
    h[1] = __floats2half2_rn(v0.z, v0.w);
    h[2] = __floats2half2_rn(v1.x, v1.y);
    h[3] = __floats2half2_rn(v1.z, v1.w);
    *(uint4*)(g_xh + i) = *(uint4*)h;
}

// wg/wu: [E][D][F] fp32 -> [E][D/2][F] half2 (pair over D)
__global__ void conv_gu(const float* __restrict__ wg, const float* __restrict__ wu) {
    int id = blockIdx.x * blockDim.x + threadIdx.x;
    int e   = id / (D2 * (FDIM / 4));
    int rem = id % (D2 * (FDIM / 4));
    int d2  = rem / (FDIM / 4);
    int f   = (rem % (FDIM / 4)) * 4;
    size_t ibase = ((size_t)e * DIM + 2 * d2) * FDIM + f;
    size_t obase = ((size_t)e * D2 + d2) * FDIM + f;
    {
        float4 a0 = *(const float4*)(wg + ibase);
        float4 a1 = *(const float4*)(wg + ibase + FDIM);
        __half2 h[4];
        h[0] = __floats2half2_rn(a0.x, a1.x);
        h[1] = __floats2half2_rn(a0.y, a1.y);
        h[2] = __floats2half2_rn(a0.z, a1.z);
        h[3] = __floats2half2_rn(a0.w, a1.w);
        *(uint4*)(g_wgi + obase) = *(uint4*)h;
    }
    {
        float4 a0 = *(const float4*)(wu + ibase);
        float4 a1 = *(const float4*)(wu + ibase + FDIM);
        __half2 h[4];
        h[0] = __floats2half2_rn(a0.x, a1.x);
        h[1] = __floats2half2_rn(a0.y, a1.y);
        h[2] = __floats2half2_rn(a0.z, a1.z);
        h[3] = __floats2half2_rn(a0.w, a1.w);
        *(uint4*)(g_wui + obase) = *(uint4*)h;
    }
}

// wd: [E][F][D] fp32 -> [E][F/2][D] half2 (pair over F)
__global__ void conv_wd(const float* __restrict__ wd) {
    int id = blockIdx.x * blockDim.x + threadIdx.x;
    int e   = id / (F2 * (DIM / 4));
    int rem = id % (F2 * (DIM / 4));
    int f2  = rem / (DIM / 4);
    int d   = (rem % (DIM / 4)) * 4;
    size_t ibase = ((size_t)e * FDIM + 2 * f2) * DIM + d;
    float4 a0 = *(const float4*)(wd + ibase);
    float4 a1 = *(const float4*)(wd + ibase + DIM);
    __half2 h[4];
    h[0] = __floats2half2_rn(a0.x, a1.x);
    h[1] = __floats2half2_rn(a0.y, a1.y);
    h[2] = __floats2half2_rn(a0.z, a1.z);
    h[3] = __floats2half2_rn(a0.w, a1.w);
    *(uint4*)(g_wdi + ((size_t)e * F2 + f2) * DIM + d) = *(uint4*)h;
}

// ---------------------------------------------------------------------------
// router: logits -> softmax -> top2 -> renorm -> scatter to expert lists
// ---------------------------------------------------------------------------
__global__ void router_kernel(const float* __restrict__ x,
                              const float* __restrict__ gw) {
    int t   = blockIdx.x;
    int tid = threadIdx.x;

    float p[NEXP];
#pragma unroll
    for (int e = 0; e < NEXP; e++) p[e] = 0.0f;

    const float* xr = x + (size_t)t * DIM;
    for (int d = tid; d < DIM; d += 128) {
        float xv = xr[d];
#pragma unroll
        for (int e = 0; e < NEXP; e++) p[e] += xv * gw[e * DIM + d];
    }

    __shared__ float sm[NEXP][128];
#pragma unroll
    for (int e = 0; e < NEXP; e++) sm[e][tid] = p[e];
    __syncthreads();

    for (int s = 64; s > 0; s >>= 1) {
        if (tid < s) {
#pragma unroll
            for (int e = 0; e < NEXP; e++) sm[e][tid] += sm[e][tid + s];
        }
        __syncthreads();
    }

    if (tid == 0) {
        float lg[NEXP];
        float mx = -1e30f;
#pragma unroll
        for (int e = 0; e < NEXP; e++) { lg[e] = sm[e][0]; mx = fmaxf(mx, lg[e]); }
        float pr[NEXP];
#pragma unroll
        for (int e = 0; e < NEXP; e++) pr[e] = expf(lg[e] - mx);
        int e0 = 0;
#pragma unroll
        for (int e = 1; e < NEXP; e++) if (pr[e] > pr[e0]) e0 = e;
        int e1 = (e0 == 0) ? 1 : 0;
#pragma unroll
        for (int e = 0; e < NEXP; e++)
            if (e != e0 && pr[e] > pr[e1]) e1 = e;
        float denom = pr[e0] + pr[e1];
        float w0 = pr[e0] / denom;
        float w1 = pr[e1] / denom;
        int p0 = atomicAdd(&g_cnt[e0], 1);
        g_tok[e0][p0] = t;          g_wt[e0][p0] = w0;   // which = 0
        int p1 = atomicAdd(&g_cnt[e1], 1);
        g_tok[e1][p1] = t | 4096;   g_wt[e1][p1] = w1;   // which = 1
    }
}

// ---------------------------------------------------------------------------
#define AW 40    // A row: 40 halves (80B) -> LDSM 16 rows hit 8 distinct bank-quads, 2 wavefronts
#define BW 136   // B row: 136 half2 -> stride mod 32 == 8, conflict-free

// ---------------------------------------------------------------------------
// gate+up GEMM: 128 x 128(per matrix) x 32, fp16, 3-stage cp.async, ldmatrix A
// 512 threads, 16 warps (2M x 8N), warp tile 64x16 per matrix; dynamic smem
// ---------------------------------------------------------------------------
#define GU_S 3
#define GU_A_BYTES (128 * AW * 2)        // 10240
#define GU_B_BYTES (16 * BW * 4)         // 8704
#define GU_SMEM (GU_S * (GU_A_BYTES + 2 * GU_B_BYTES))   // 82944

__global__ void __launch_bounds__(512, 1)
gateup_mma() {
    extern __shared__ char dsm[];
    __half*  As = (__half*)dsm;                                       // [GU_S][128*AW]
    __half2* Bg = (__half2*)(dsm + GU_S * GU_A_BYTES);                // [GU_S][16*BW]
    __half2* Bu = (__half2*)(dsm + GU_S * (GU_A_BYTES + GU_B_BYTES)); // [GU_S][16*BW]

    __shared__ int   stok[128];
    __shared__ float swt[128];

    int e   = blockIdx.z;
    int cnt = g_cnt[e];
    int m0  = blockIdx.y * 128;
    if (m0 >= cnt) return;
    int n0  = blockIdx.x * 128;

    int tid = threadIdx.x;
    if (tid < 128) {
        int m = m0 + tid;
        int v = (m < cnt) ? g_tok[e][m] : 0;
        stok[tid] = v & 4095;
        swt[tid]  = (m < cnt) ? g_wt[e][m] : 0.0f;
    }
    __syncthreads();

    const __half2* wgE = g_wgi + (size_t)e * D2 * FDIM;
    const __half2* wuE = g_wui + (size_t)e * D2 * FDIM;

    int wid  = tid >> 5, lane = tid & 31;
    int gid  = lane >> 2, tig = lane & 3;
    int warpM = wid & 1, warpN = wid >> 1;       // 2 x 8 warps
    int wm = warpM * 64, wn = warpN * 16;

    // fill assignments: every thread does 1 A + 1 Bg + 1 Bu chunk (16B each)
    int arow = tid >> 2, acol = (tid & 3) * 8;           // A: 128 rows x 4 chunks
    int bkr  = tid >> 5, bn = (tid & 31) * 4;            // B: 16 rows x 32 chunks

    // ldmatrix lane address pieces
    int lrow = wm + (lane & 15), lchunk = (lane >> 4) * 8;

    const __half* xr0 = g_xh + (size_t)stok[arow] * DIM + acol;

    float cg[4][2][4] = {}, cu[4][2][4] = {};

    const int KT = DIM / 32;     // 64

    // prologue
#pragma unroll
    for (int s = 0; s < GU_S - 1; s++) {
        int kb = s * 32, kb2 = s * 16;
        cp16(&As[s * 128 * AW + arow * AW + acol], xr0 + kb);
        cp16(&Bg[s * 16 * BW + bkr * BW + bn], wgE + (size_t)(kb2 + bkr) * FDIM + n0 + bn);
        cp16(&Bu[s * 16 * BW + bkr * BW + bn], wuE + (size_t)(kb2 + bkr) * FDIM + n0 + bn);
        cp_commit();
    }

    for (int kt = 0; kt < KT; kt++) {
        cp_wait<GU_S - 2>();
        __syncthreads();

        int ln = kt + GU_S - 1;
        if (ln < KT) {
            int s = ln % GU_S;
            int kb = ln * 32, kb2 = ln * 16;
            cp16(&As[s * 128 * AW + arow * AW + acol], xr0 + kb);
            cp16(&Bg[s * 16 * BW + bkr * BW + bn], wgE + (size_t)(kb2 + bkr) * FDIM + n0 + bn);
            cp16(&Bu[s * 16 * BW + bkr * BW + bn], wuE + (size_t)(kb2 + bkr) * FDIM + n0 + bn);
        }
        cp_commit();

        int cs = kt % GU_S;
        const __half*  Ac = As + cs * 128 * AW;
        const __half2* Gc = Bg + cs * 16 * BW;
        const __half2* Uc = Bu + cs * 16 * BW;
#pragma unroll
        for (int ks = 0; ks < 2; ks++) {
            unsigned abase = (unsigned)__cvta_generic_to_shared(
                &Ac[lrow * AW + ks * 16 + lchunk]);
            unsigned a[4][4];
#pragma unroll
            for (int mi = 0; mi < 4; mi++)
                ldsm4(a[mi], abase + (unsigned)(mi * 16 * AW * 2));
#pragma unroll
            for (int ni = 0; ni < 2; ni++) {
                int nc = wn + ni * 8 + gid;
                unsigned bg0 = *(const unsigned*)&Gc[(ks * 8 + tig    ) * BW + nc];
                unsigned bg1 = *(const unsigned*)&Gc[(ks * 8 + tig + 4) * BW + nc];
                unsigned bu0 = *(const unsigned*)&Uc[(ks * 8 + tig    ) * BW + nc];
                unsigned bu1 = *(const unsigned*)&Uc[(ks * 8 + tig + 4) * BW + nc];
#pragma unroll
                for (int mi = 0; mi < 4; mi++) {
                    mma_f16(cg[mi][ni], a[mi], bg0, bg1);
                    mma_f16(cu[mi][ni], a[mi], bu0, bu1);
                }
            }
        }
    }

    // epilogue: SiLU(g)*u*w -> g_h (half)
#pragma unroll
    for (int mi = 0; mi < 4; mi++) {
#pragma unroll
        for (int half = 0; half < 2; half++) {
            int lm = wm + mi * 16 + gid + half * 8;
            int m  = m0 + lm;
            if (m >= cnt) continue;
            float w = swt[lm];
            __half* hrow = g_h + ((size_t)e * T_TOK + m) * FDIM + n0;
#pragma unroll
            for (int ni = 0; ni < 2; ni++) {
                int col = wn + ni * 8 + 2 * tig;
                float g0 = cg[mi][ni][half * 2 + 0], g1 = cg[mi][ni][half * 2 + 1];
                float u0 = cu[mi][ni][half * 2 + 0], u1 = cu[mi][ni][half * 2 + 1];
                float h0 = (g0 / (1.0f + __expf(-g0))) * u0 * w;
                float h1 = (g1 / (1.0f + __expf(-g1))) * u1 * w;
                *(__half2*)(hrow + col) = __floats2half2_rn(h0, h1);
            }
        }
    }
}

// ---------------------------------------------------------------------------
// down GEMM: 128 x 128 x 32, fp16, 3-stage cp.async, 2 CTAs/SM, ldmatrix A
// 256 threads, 8 warps (2M x 4N), warp tile 64x32; dynamic smem
// writes contribution rows to g_c (no atomics)
// ---------------------------------------------------------------------------
#define DN_S 3
#define DN_A_BYTES (128 * AW * 2)        // 10240
#define DN_B_BYTES (16 * BW * 4)         // 8704
#define DN_SMEM (DN_S * (DN_A_BYTES + DN_B_BYTES))   // 56832

__global__ void __launch_bounds__(256, 2)
down_mma() {
    extern __shared__ char dsm[];
    __half*  As = (__half*)dsm;                         // [DN_S][128*AW]
    __half2* Bd = (__half2*)(dsm + DN_S * DN_A_BYTES);  // [DN_S][16*BW]

    __shared__ int stok[128];

    int e   = blockIdx.z;
    int cnt = g_cnt[e];
    int m0  = blockIdx.y * 128;
    if (m0 >= cnt) return;
    int n0  = blockIdx.x * 128;

    int tid = threadIdx.x;
    if (tid < 128) {
        int m = m0 + tid;
        stok[tid] = (m < cnt) ? g_tok[e][m] : 0;
    }
    __syncthreads();

    const __half2* wdE = g_wdi + (size_t)e * F2 * DIM;
    const __half*  hE  = g_h + (size_t)e * T_TOK * FDIM;

    int wid  = tid >> 5, lane = tid & 31;
    int gid  = lane >> 2, tig = lane & 3;
    int warpM = wid & 1, warpN = wid >> 1;
    int wm = warpM * 64, wn = warpN * 32;

    // fill assignments: 2 A chunks + 2 B chunks per thread
    int arow = tid >> 1, acol = (tid & 1) * 16;          // A: 2 chunks at acol, acol+8
    int bkr  = tid >> 4, bn = (tid & 15) * 8;            // B: 2 chunks at bn, bn+4 (half2 units)
    int lrow = wm + (lane & 15), lchunk = (lane >> 4) * 8;

    const __half* hr0 = hE + (size_t)((m0 + arow) & 4095) * FDIM + acol;

    float c[4][4][4] = {};

    const int KT = FDIM / 32;    // 44

    // prologue
#pragma unroll
    for (int s = 0; s < DN_S - 1; s++) {
        int kb = s * 32, kb2 = s * 16;
        cp16(&As[s * 128 * AW + arow * AW + acol],     hr0 + kb);
        cp16(&As[s * 128 * AW + arow * AW + acol + 8], hr0 + kb + 8);
        cp16(&Bd[s * 16 * BW + bkr * BW + bn],     wdE + (size_t)(kb2 + bkr) * DIM + n0 + bn);
        cp16(&Bd[s * 16 * BW + bkr * BW + bn + 4], wdE + (size_t)(kb2 + bkr) * DIM + n0 + bn + 4);
        cp_commit();
    }

    for (int kt = 0; kt < KT; kt++) {
        cp_wait<DN_S - 2>();
        __syncthreads();

        int ln = kt + DN_S - 1;
        if (ln < KT) {
            int s = ln % DN_S;
            int kb = ln * 32, kb2 = ln * 16;
            cp16(&As[s * 128 * AW + arow * AW + acol],     hr0 + kb);
            cp16(&As[s * 128 * AW + arow * AW + acol + 8], hr0 + kb + 8);
            cp16(&Bd[s * 16 * BW + bkr * BW + bn],     wdE + (size_t)(kb2 + bkr) * DIM + n0 + bn);
            cp16(&Bd[s * 16 * BW + bkr * BW + bn + 4], wdE + (size_t)(kb2 + bkr) * DIM + n0 + bn + 4);
        }
        cp_commit();

        int cs = kt % DN_S;
        const __half*  Ac = As + cs * 128 * AW;
        const __half2* Dc = Bd + cs * 16 * BW;
#pragma unroll
        for (int ks = 0; ks < 2; ks++) {
            unsigned abase = (unsigned)__cvta_generic_to_shared(
                &Ac[lrow * AW + ks * 16 + lchunk]);
            unsigned a[4][4];
#pragma unroll
            for (int mi = 0; mi < 4; mi++)
                ldsm4(a[mi], abase + (unsigned)(mi * 16 * AW * 2));
#pragma unroll
            for (int ni = 0; ni < 4; ni++) {
                int nc = wn + ni * 8 + gid;
                unsigned b0 = *(const unsigned*)&Dc[(ks * 8 + tig    ) * BW + nc];
                unsigned b1 = *(const unsigned*)&Dc[(ks * 8 + tig + 4) * BW + nc];
#pragma unroll
                for (int mi = 0; mi < 4; mi++) {
                    mma_f16(c[mi][ni], a[mi], b0, b1);
                }
            }
        }
    }

    // epilogue: write contribution rows (plain stores, no atomics)
#pragma unroll
    for (int mi = 0; mi < 4; mi++) {
#pragma unroll
        for (int half = 0; half < 2; half++) {
            int lm = wm + mi * 16 + gid + half * 8;
            int m  = m0 + lm;
            if (m >= cnt) continue;
            int v = stok[lm];
            int tok = v & 4095, which = v >> 12;
            float* crow = &g_c[which][(size_t)tok * DIM + n0];
#pragma unroll
            for (int ni = 0; ni < 4; ni++) {
                int col = wn + ni * 8 + 2 * tig;
                float2 o;
                o.x = c[mi][ni][half * 2 + 0];
                o.y = c[mi][ni][half * 2 + 1];
                *(float2*)(crow + col) = o;
            }
        }
    }
}

// ---------------------------------------------------------------------------
// combine: out[t] = contrib[0][t] + contrib[1][t]  (fixed order, deterministic)
// ---------------------------------------------------------------------------
__global__ void combine_kernel(float* __restrict__ out) {
    size_t i = ((size_t)blockIdx.x * blockDim.x + threadIdx.x) * 4;
    float4 a = *(const float4*)&g_c[0][i];
    float4 b = *(const float4*)&g_c[1][i];
    float4 o;
    o.x = a.x + b.x; o.y = a.y + b.y; o.z = a.z + b.z; o.w = a.w + b.w;
    *(float4*)(out + i) = o;
}

// ---------------------------------------------------------------------------
extern "C" void kernel_launch(void* const* d_in, const int* in_sizes, int n_in,
                              void* d_out, int out_size) {
    const float* x  = (const float*)d_in[0];   // [T, D]
    const float* gw = (const float*)d_in[1];   // [E, D]
    const float* wg = (const float*)d_in[2];   // [E, D, F]
    const float* wu = (const float*)d_in[3];   // [E, D, F]
    const float* wd = (const float*)d_in[4];   // [E, F, D]
    float* out = (float*)d_out;

    cudaFuncSetAttribute(gateup_mma, cudaFuncAttributeMaxDynamicSharedMemorySize, GU_SMEM);
    cudaFuncSetAttribute(down_mma,   cudaFuncAttributeMaxDynamicSharedMemorySize, DN_SMEM);

    conv_x<<<(T_TOK * DIM / 8 + 255) / 256, 256>>>(x);
    conv_gu<<<(NEXP * D2 * (FDIM / 4) + 255) / 256, 256>>>(wg, wu);
    conv_wd<<<(NEXP * F2 * (DIM / 4) + 255) / 256, 256>>>(wd);
    router_kernel<<<T_TOK, 128>>>(x, gw);

    dim3 g2(FDIM / 128, T_TOK / 128, NEXP);   // (11, 16, 8)
    gateup_mma<<<g2, 512, GU_SMEM>>>();

    dim3 g3(DIM / 128, T_TOK / 128, NEXP);    // (16, 16, 8)
    down_mma<<<g3, 256, DN_SMEM>>>();

    combine_kernel<<<(T_TOK * DIM) / (256 * 4), 256>>>(out);
}